// round 12
// baseline (speedup 1.0000x reference)
#include <cuda_runtime.h>
#include <math.h>
#include <stdint.h>

// Problem constants
#define BSZ   2
#define TSZ   2048
#define CSZ   1024
#define NH    16
#define HSD   64
#define NC3   3072   // 3*C

// Scratch: qkv = x @ W + b   [B, T, 3C]
__device__ float g_qkv[(size_t)BSZ * TSZ * NC3];
// Prebuilt GEMM operand fragment images (tf32 bits)
__device__ uint32_t g_afrag[(size_t)32 * 32 * 4096];   // [m_blk][chunk][16KB]
__device__ uint32_t g_bfrag[(size_t)24 * 32 * 4096];   // [n_blk][chunk][16KB]
// Q fragment images: [b][h][qt:16][32KB]  (A-frag layout, scaled QSCALE)
__device__ uint32_t g_qfrag[(size_t)BSZ * NH * 16 * 8192];
// K/V fragment images: [b][h][kt:32][32KB] (K 16KB + V 16KB, paired layout)
__device__ uint32_t g_kvfrag[(size_t)BSZ * NH * 32 * 8192];

// Q pre-scale: (1/sqrt(64)) * log2(e)  -> softmax runs in exp2 domain
#define QSCALE 0.18033688011112042f

// ===========================================================================
// helpers
// ===========================================================================
__device__ __forceinline__ uint32_t f2tf32(float f) {
  uint32_t r;
  asm("cvt.rna.tf32.f32 %0, %1;" : "=r"(r) : "f"(f));
  return r;
}
__device__ __forceinline__ float ex2f(float x) {
  float r;
  asm("ex2.approx.f32 %0, %1;" : "=f"(r) : "f"(x));
  return r;
}
__device__ __forceinline__ int uswz(int lane) {
  int q = lane >> 2;
  return (q << 2) | ((lane + q + (q >> 2)) & 3);
}
__device__ __forceinline__ uint32_t smem_u32(const void* p) {
  uint32_t a;
  asm("{ .reg .u64 t; cvta.to.shared.u64 t, %1; cvt.u32.u64 %0, t; }"
      : "=r"(a) : "l"(p));
  return a;
}
#define MMA_TF32(d, a, b)                                                  \
  asm volatile(                                                            \
      "mma.sync.aligned.m16n8k8.row.col.f32.tf32.tf32.f32 "                \
      "{%0,%1,%2,%3}, {%4,%5,%6,%7}, {%8,%9}, {%0,%1,%2,%3};"              \
      : "+f"((d)[0]), "+f"((d)[1]), "+f"((d)[2]), "+f"((d)[3])             \
      : "r"((a).x), "r"((a).y), "r"((a).z), "r"((a).w),                    \
        "r"((b).x), "r"((b).y))
#define MMA_TF32R(d, a, b0r, b1r)                                          \
  asm volatile(                                                            \
      "mma.sync.aligned.m16n8k8.row.col.f32.tf32.tf32.f32 "                \
      "{%0,%1,%2,%3}, {%4,%5,%6,%7}, {%8,%9}, {%0,%1,%2,%3};"              \
      : "+f"((d)[0]), "+f"((d)[1]), "+f"((d)[2]), "+f"((d)[3])             \
      : "r"((a).x), "r"((a).y), "r"((a).z), "r"((a).w),                    \
        "r"(b0r), "r"(b1r))
#define CP_ASYNC16(dst, src)                                               \
  asm volatile("cp.async.cg.shared.global [%0], [%1], 16;"                 \
               :: "r"(dst), "l"(src))
#define CP_COMMIT() asm volatile("cp.async.commit_group;" ::: "memory")
#define CP_WAIT0()  asm volatile("cp.async.wait_group 0;" ::: "memory")
#define CP_WAIT1()  asm volatile("cp.async.wait_group 1;" ::: "memory")

// ===========================================================================
// Kernel 0: build GEMM operand fragment images from x and W (unchanged).
// ===========================================================================
__global__ __launch_bounds__(256) void gemm_frag_prep_kernel(
    const float* __restrict__ A,
    const float* __restrict__ W) {
  const int tid = threadIdx.x;
  const int c = blockIdx.x;            // k-chunk 0..31
  if (blockIdx.y < 32) {
    const int m0 = blockIdx.y * 128;
    const int k0 = c * 32;
    const int a_tile = tid >> 5;
    const int a_ks   = (tid >> 3) & 3;
    const int a_q    = tid & 7;
    const int perm = (a_q + (a_q >> 2)) & 3;
    const float* ap =
        A + (size_t)(m0 + a_tile * 16 + a_q) * CSZ + k0 + a_ks * 8;
    float4 r0a = *(const float4*)(ap);
    float4 r0b = *(const float4*)(ap + 4);
    float4 r1a = *(const float4*)(ap + 8 * CSZ);
    float4 r1b = *(const float4*)(ap + 8 * CSZ + 4);
    const float r0[8] = {r0a.x, r0a.y, r0a.z, r0a.w, r0b.x, r0b.y, r0b.z, r0b.w};
    const float r1[8] = {r1a.x, r1a.y, r1a.z, r1a.w, r1b.x, r1b.y, r1b.z, r1b.w};
    char* dst = (char*)g_afrag + ((size_t)(blockIdx.y * 32 + c)) * 16384 +
                (a_tile * 4 + a_ks) * 512;
#pragma unroll
    for (int j = 0; j < 4; j++) {
      uint4 v;
      v.x = f2tf32(r0[j]);
      v.y = f2tf32(r1[j]);
      v.z = f2tf32(r0[j + 4]);
      v.w = f2tf32(r1[j + 4]);
      *(uint4*)(dst + (4 * a_q + ((j + perm) & 3)) * 16) = v;
    }
  } else {
    const int n_blk = blockIdx.y - 32;
    const int n0 = n_blk * 128;
    const int k0 = c * 32;
#pragma unroll
    for (int i = 0; i < 2; i++) {
      const int u = tid + i * 256;
      const int nh = u & 1;
      const int kk = (u >> 1) & 3;
      const int ks = (u >> 3) & 3;
      const int nt = u >> 5;
      const float* bp = W + (size_t)(k0 + ks * 8 + kk) * NC3 + n0 +
                        nt * 8 + nh * 4;
      float4 b0 = *(const float4*)(bp);
      float4 b1 = *(const float4*)(bp + 4 * NC3);
      const float f0[4] = {b0.x, b0.y, b0.z, b0.w};
      const float f1[4] = {b1.x, b1.y, b1.z, b1.w};
      char* dst = (char*)g_bfrag + ((size_t)(n_blk * 32 + c)) * 16384 +
                  (nt * 4 + ks) * 256;
#pragma unroll
      for (int j = 0; j < 4; j++) {
        const int q = nh * 4 + j;
        const int slot = 4 * q + ((kk + q + (q >> 2)) & 3);
        uint2 v;
        v.x = f2tf32(f0[j]);
        v.y = f2tf32(f1[j]);
        *(uint2*)(dst + slot * 8) = v;
      }
    }
  }
}

// ===========================================================================
// Kernel 1: QKV GEMM from prebuilt fragments (coalesced f32 epilogue).
// ===========================================================================
#define GCHUNK 32768
#define GSMEM_TOTAL (3 * GCHUNK)
#define NCHUNK 32

__global__ __launch_bounds__(256, 2) void qkv_gemm_mma_kernel(
    const float* __restrict__ bias) {
  extern __shared__ char smem[];
  const uint32_t sb = smem_u32(smem);
  const int tid  = threadIdx.x;
  const int lane = tid & 31;
  const int warp = tid >> 5;
  const int wm = warp >> 2;
  const int wn = warp & 3;
  const int m0 = blockIdx.y * 128;
  const int n0 = blockIdx.x * 128;

  const char* asrc0 =
      (const char*)g_afrag + ((size_t)blockIdx.y * 32) * 16384;
  const char* bsrc0 =
      (const char*)g_bfrag + ((size_t)blockIdx.x * 32) * 16384;

  const int rl16 = uswz(lane) * 16;
  const int rl8  = uswz(lane) * 8;

  float acc[4][4][4] = {};

#pragma unroll
  for (int i = 0; i < 4; i++) {
    const int off = tid * 16 + i * 4096;
    CP_ASYNC16(sb + off, asrc0 + off);
    CP_ASYNC16(sb + 16384 + off, bsrc0 + off);
  }
  CP_COMMIT();

  for (int c = 0; c < NCHUNK; c++) {
    if (c + 1 < NCHUNK) {
      const uint32_t dst = sb + ((c + 1) % 3) * GCHUNK;
      const char* as = asrc0 + (size_t)(c + 1) * 16384;
      const char* bs = bsrc0 + (size_t)(c + 1) * 16384;
#pragma unroll
      for (int i = 0; i < 4; i++) {
        const int off = tid * 16 + i * 4096;
        CP_ASYNC16(dst + off, as + off);
        CP_ASYNC16(dst + 16384 + off, bs + off);
      }
      CP_COMMIT();
      CP_WAIT1();
    } else {
      CP_WAIT0();
    }
    __syncthreads();

    const char* ab = smem + (c % 3) * GCHUNK;
    const char* bb = ab + 16384;
#pragma unroll
    for (int ks = 0; ks < 4; ks++) {
      uint4 af[4];
      uint2 bf[4];
#pragma unroll
      for (int mi = 0; mi < 4; mi++)
        af[mi] = *(const uint4*)(ab + ((wm * 4 + mi) * 4 + ks) * 512 + rl16);
#pragma unroll
      for (int ni = 0; ni < 4; ni++)
        bf[ni] = *(const uint2*)(bb + ((wn * 4 + ni) * 4 + ks) * 256 + rl8);
#pragma unroll
      for (int mi = 0; mi < 4; mi++)
#pragma unroll
        for (int ni = 0; ni < 4; ni++)
          MMA_TF32(acc[mi][ni], af[mi], bf[ni]);
    }
  }

  // epilogue: acc + bias -> g_qkv  (coalesced float2 stores)
  const int r_base = m0 + wm * 64 + (lane >> 2);
  const int c_base = n0 + wn * 32 + 2 * (lane & 3);
#pragma unroll
  for (int ni = 0; ni < 4; ni++) {
    const int gc = c_base + ni * 8;
    float2 bv = *(const float2*)&bias[gc];
#pragma unroll
    for (int mi = 0; mi < 4; mi++) {
      const int gr = r_base + mi * 16;
      float2 o0 = make_float2(acc[mi][ni][0] + bv.x, acc[mi][ni][1] + bv.y);
      float2 o1 = make_float2(acc[mi][ni][2] + bv.x, acc[mi][ni][3] + bv.y);
      *(float2*)&g_qkv[(size_t)gr * NC3 + gc] = o0;
      *(float2*)&g_qkv[(size_t)(gr + 8) * NC3 + gc] = o1;
    }
  }
}

// ===========================================================================
// Kernel 1.5: build Q / K / V fragment images from g_qkv (R9 version,
// Q scaled by QSCALE for exp2-domain softmax).
// Grid (48, 16, 2): x<16 -> Q tile qt=x; x>=16 -> KV tile kt=x-16.
// ===========================================================================
__global__ __launch_bounds__(256) void qkv_frag_prep_kernel() {
  __shared__ uint32_t vsm[4096];   // 16KB V image staging
  const int tid = threadIdx.x;
  const int h = blockIdx.y;
  const int b = blockIdx.z;
  const float* qkv = g_qkv;

  if (blockIdx.x < 16) {
    const int qt = blockIdx.x;
    const int q0 = qt * 128;
    char* qimg = (char*)g_qfrag + ((size_t)((b * NH + h) * 16 + qt)) * 32768;
#pragma unroll
    for (int i = 0; i < 2; i++) {
      const int u = tid + i * 256;
      const int wt = u >> 6, ks = (u >> 3) & 7, q = u & 7;
      const float* qp = qkv + (size_t)(b * TSZ + q0 + wt * 16 + q) * NC3 +
                        h * HSD + ks * 8;
      float4 r0a = *(const float4*)(qp);
      float4 r0b = *(const float4*)(qp + 4);
      float4 r1a = *(const float4*)(qp + (size_t)8 * NC3);
      float4 r1b = *(const float4*)(qp + (size_t)8 * NC3 + 4);
      const float r0[8] = {r0a.x, r0a.y, r0a.z, r0a.w,
                           r0b.x, r0b.y, r0b.z, r0b.w};
      const float r1[8] = {r1a.x, r1a.y, r1a.z, r1a.w,
                           r1b.x, r1b.y, r1b.z, r1b.w};
      char* dst = qimg + (wt * 8 + ks) * 512 + q * 64;
#pragma unroll
      for (int j = 0; j < 4; j++) {
        uint4 v;
        v.x = f2tf32(r0[j] * QSCALE);
        v.y = f2tf32(r1[j] * QSCALE);
        v.z = f2tf32(r0[j + 4] * QSCALE);
        v.w = f2tf32(r1[j + 4] * QSCALE);
        *(uint4*)(dst + j * 16) = v;
      }
    }
  } else {
    const int kt = blockIdx.x - 16;
    const int k0 = kt * 64;
    char* kvimg = (char*)g_kvfrag + ((size_t)((b * NH + h) * 32 + kt)) * 32768;

    // K: one unit per thread, 64B LDG -> 64B STG, fully coalesced
    {
      const int nt = tid >> 5, ksp = (tid >> 3) & 3, tq = tid & 7;
      const float* kp = qkv + (size_t)(b * TSZ + k0 + nt * 8 + tq) * NC3 +
                        CSZ + h * HSD + ksp * 16;
      float f[16];
      *(float4*)(f)      = *(const float4*)(kp);
      *(float4*)(f + 4)  = *(const float4*)(kp + 4);
      *(float4*)(f + 8)  = *(const float4*)(kp + 8);
      *(float4*)(f + 12) = *(const float4*)(kp + 12);
      char* dst = kvimg + (nt * 4 + ksp) * 512 + tq * 64;
#pragma unroll
      for (int c = 0; c < 4; c++) {
        uint4 v;
        v.x = f2tf32(f[c]);
        v.y = f2tf32(f[4 + c]);
        v.z = f2tf32(f[8 + c]);
        v.w = f2tf32(f[12 + c]);
        *(uint4*)(dst + c * 16) = v;
      }
    }

    // V: scalar scatter into smem (paired layout), then linear copy
#pragma unroll
    for (int i = 0; i < 2; i++) {
      const int u = tid + i * 256;
      const int nd = u >> 6, kso = (u >> 3) & 7, tq = u & 7;
      const float* vp = qkv + (size_t)(b * TSZ + k0 + kso * 8 + tq) * NC3 +
                        2 * CSZ + h * HSD + nd * 8;
      float4 va = *(const float4*)(vp);
      float4 vb = *(const float4*)(vp + 4);
      const float vv[8] = {va.x, va.y, va.z, va.w, vb.x, vb.y, vb.z, vb.w};
      const int gw  = (nd * 4 + (kso >> 1)) * 128;   // group word base
      const int wrd = (kso & 1) * 2 + (tq >> 2);
#pragma unroll
      for (int dq = 0; dq < 8; dq++) {
        vsm[gw + (dq * 4 + (tq & 3)) * 4 + wrd] = f2tf32(vv[dq]);
      }
    }
    __syncthreads();
    uint4* dst = (uint4*)(kvimg + 16384);
    const uint4* src = (const uint4*)vsm;
#pragma unroll
    for (int i = 0; i < 4; i++) dst[tid + i * 256] = src[tid + i * 256];
  }
}

// ===========================================================================
// Kernel 2: flash attention — paired K/V LDS.128 reads, NO Q preload
// (Q fragments loaded per-ksp inside the loop: low register pressure),
// exp2-domain softmax.  Smem: Qf 32KB + 2x32KB KV = 96KB.
// ===========================================================================
#define FTQ 128
#define FTK 64
#define FBUF0 32768
#define FSMEM (96 * 1024)

__global__ __launch_bounds__(256, 2) void flash_attn_mma_kernel(
    float* __restrict__ out) {
  extern __shared__ char fsm[];
  const uint32_t sb = smem_u32(fsm);
  const int tid  = threadIdx.x;
  const int lane = tid & 31;
  const int warp = tid >> 5;
  const int qt = gridDim.x - 1 - blockIdx.x;   // heavy tiles first
  const int h  = blockIdx.y;
  const int b  = blockIdx.z;
  const int q0 = qt * FTQ;
  const char* qimg =
      (const char*)g_qfrag + ((size_t)((b * NH + h) * 16 + qt)) * 32768;
  const char* tiles =
      (const char*)g_kvfrag + ((size_t)((b * NH + h) * 32)) * 32768;

  // prologue: Q frag image + KV tile 0
#pragma unroll
  for (int i = 0; i < 8; i++) {
    const int c = (tid + i * 256) * 16;
    CP_ASYNC16(sb + c, qimg + c);
    CP_ASYNC16(sb + FBUF0 + c, tiles + c);
  }
  CP_COMMIT();
  CP_WAIT0();
  __syncthreads();

  float m0 = -1e30f, m1 = -1e30f, l0 = 0.f, l1 = 0.f;
  float o[8][4] = {};
  const int wrow0 = q0 + warp * 16;
  const int r0g = wrow0 + (lane >> 2);
  const int r1g = r0g + 8;
  const int lr2 = 2 * (lane & 3);
  const int last_kt = 2 * qt + 1;

  for (int kt = 0; kt <= last_kt; kt++) {
    const int cur = kt & 1;

    if (kt < last_kt) {
      const char* src = tiles + (size_t)(kt + 1) * 32768;
      const uint32_t dst = sb + FBUF0 + (1 - cur) * 32768;
#pragma unroll
      for (int i = 0; i < 8; i++) {
        const int c = (tid + i * 256) * 16;
        CP_ASYNC16(dst + c, src + c);
      }
      CP_COMMIT();
    }

    const int k0 = kt * FTK;
    if (k0 <= wrow0 + 15) {
      const char* kf = fsm + FBUF0 + cur * 32768;
      const char* vf = kf + 16384;
      const bool full = (k0 + 63 <= wrow0);
      const int ntmax = full ? 8 : (((wrow0 + 15 - k0) >> 3) + 1);

      // ---- S = Q K^T  (Q loaded per-ksp: 8 live Q regs, not 32) ----
      float s[8][4];
#pragma unroll
      for (int nt = 0; nt < 8; nt++)
        s[nt][0] = s[nt][1] = s[nt][2] = s[nt][3] = 0.f;

      if (full) {
#pragma unroll
        for (int ksp = 0; ksp < 4; ksp++) {
          uint4 qa = *(const uint4*)(fsm + (warp * 8 + 2 * ksp) * 512 +
                                     lane * 16);
          uint4 qb = *(const uint4*)(fsm + (warp * 8 + 2 * ksp + 1) * 512 +
                                     lane * 16);
#pragma unroll
          for (int nt = 0; nt < 8; nt++) {
            uint4 kf4 = *(const uint4*)(kf + (nt * 4 + ksp) * 512 + lane * 16);
            MMA_TF32R(s[nt], qa, kf4.x, kf4.y);
            MMA_TF32R(s[nt], qb, kf4.z, kf4.w);
          }
        }
      } else {
#pragma unroll
        for (int ksp = 0; ksp < 4; ksp++) {
          uint4 qa = *(const uint4*)(fsm + (warp * 8 + 2 * ksp) * 512 +
                                     lane * 16);
          uint4 qb = *(const uint4*)(fsm + (warp * 8 + 2 * ksp + 1) * 512 +
                                     lane * 16);
#pragma unroll
          for (int nt = 0; nt < 8; nt++) {
            if (nt < ntmax) {
              uint4 kf4 = *(const uint4*)(kf + (nt * 4 + ksp) * 512 +
                                          lane * 16);
              MMA_TF32R(s[nt], qa, kf4.x, kf4.y);
              MMA_TF32R(s[nt], qb, kf4.z, kf4.w);
            }
          }
        }
#pragma unroll
        for (int nt = 0; nt < 8; nt++) {
          const int cg = k0 + nt * 8 + lr2;
          if (cg     > r0g) s[nt][0] = -1e30f;
          if (cg + 1 > r0g) s[nt][1] = -1e30f;
          if (cg     > r1g) s[nt][2] = -1e30f;
          if (cg + 1 > r1g) s[nt][3] = -1e30f;
        }
      }

      // ---- online softmax in exp2 domain (register, quad-reduced) ----
      float mx0 = -1e30f, mx1 = -1e30f;
#pragma unroll
      for (int nt = 0; nt < 8; nt++) {
        mx0 = fmaxf(mx0, fmaxf(s[nt][0], s[nt][1]));
        mx1 = fmaxf(mx1, fmaxf(s[nt][2], s[nt][3]));
      }
      mx0 = fmaxf(mx0, __shfl_xor_sync(0xffffffffu, mx0, 1));
      mx0 = fmaxf(mx0, __shfl_xor_sync(0xffffffffu, mx0, 2));
      mx1 = fmaxf(mx1, __shfl_xor_sync(0xffffffffu, mx1, 1));
      mx1 = fmaxf(mx1, __shfl_xor_sync(0xffffffffu, mx1, 2));
      const float mn0 = fmaxf(m0, mx0);
      const float mn1 = fmaxf(m1, mx1);
      const float al0 = ex2f(m0 - mn0);
      const float al1 = ex2f(m1 - mn1);
      float sum0 = 0.f, sum1 = 0.f;
#pragma unroll
      for (int nt = 0; nt < 8; nt++) {
        s[nt][0] = ex2f(s[nt][0] - mn0); sum0 += s[nt][0];
        s[nt][1] = ex2f(s[nt][1] - mn0); sum0 += s[nt][1];
        s[nt][2] = ex2f(s[nt][2] - mn1); sum1 += s[nt][2];
        s[nt][3] = ex2f(s[nt][3] - mn1); sum1 += s[nt][3];
      }
      sum0 += __shfl_xor_sync(0xffffffffu, sum0, 1);
      sum0 += __shfl_xor_sync(0xffffffffu, sum0, 2);
      sum1 += __shfl_xor_sync(0xffffffffu, sum1, 1);
      sum1 += __shfl_xor_sync(0xffffffffu, sum1, 2);
      m0 = mn0; m1 = mn1;
      l0 = l0 * al0 + sum0;
      l1 = l1 * al1 + sum1;

      // ---- build P A-fragments via quad shuffles ----
      uint4 pf[8];
      const int srcA = (lane & ~3) | ((lane & 3) >> 1);
      const int srcB = srcA + 2;
      const bool hi = lane & 1;
#pragma unroll
      for (int ks = 0; ks < 8; ks++) {
        if (ks < ntmax) {
          float v0 = __shfl_sync(0xffffffffu, s[ks][0], srcA);
          float v1 = __shfl_sync(0xffffffffu, s[ks][1], srcA);
          float w0 = __shfl_sync(0xffffffffu, s[ks][0], srcB);
          float w1 = __shfl_sync(0xffffffffu, s[ks][1], srcB);
          float x0 = __shfl_sync(0xffffffffu, s[ks][2], srcA);
          float x1 = __shfl_sync(0xffffffffu, s[ks][3], srcA);
          float y0 = __shfl_sync(0xffffffffu, s[ks][2], srcB);
          float y1 = __shfl_sync(0xffffffffu, s[ks][3], srcB);
          pf[ks].x = f2tf32(hi ? v1 : v0);
          pf[ks].y = f2tf32(hi ? x1 : x0);
          pf[ks].z = f2tf32(hi ? w1 : w0);
          pf[ks].w = f2tf32(hi ? y1 : y0);
        }
      }

      // ---- O = O*alpha + P V  (paired V reads) ----
#pragma unroll
      for (int nt = 0; nt < 8; nt++) {
        o[nt][0] *= al0; o[nt][1] *= al0;
        o[nt][2] *= al1; o[nt][3] *= al1;
      }
      if (full) {
#pragma unroll
        for (int ksp = 0; ksp < 4; ksp++) {
#pragma unroll
          for (int nd = 0; nd < 8; nd++) {
            uint4 vf4 = *(const uint4*)(vf + (nd * 4 + ksp) * 512 + lane * 16);
            MMA_TF32R(o[nd], pf[2 * ksp],     vf4.x, vf4.y);
            MMA_TF32R(o[nd], pf[2 * ksp + 1], vf4.z, vf4.w);
          }
        }
      } else {
#pragma unroll
        for (int ksp = 0; ksp < 4; ksp++) {
          if (2 * ksp < ntmax) {
#pragma unroll
            for (int nd = 0; nd < 8; nd++) {
              uint4 vf4 = *(const uint4*)(vf + (nd * 4 + ksp) * 512 + lane * 16);
              MMA_TF32R(o[nd], pf[2 * ksp], vf4.x, vf4.y);
              if (2 * ksp + 1 < ntmax)
                MMA_TF32R(o[nd], pf[2 * ksp + 1], vf4.z, vf4.w);
            }
          }
        }
      }
    }

    CP_WAIT0();
    __syncthreads();
  }

  // epilogue: normalize, write out[b, q, h*64 + d]
  const float i0 = 1.f / l0;
  const float i1 = 1.f / l1;
  const int rg = q0 + warp * 16 + (lane >> 2);
#pragma unroll
  for (int nd = 0; nd < 8; nd++) {
    const int gc = h * HSD + nd * 8 + lr2;
    float2 w0 = make_float2(o[nd][0] * i0, o[nd][1] * i0);
    float2 w1 = make_float2(o[nd][2] * i1, o[nd][3] * i1);
    *(float2*)&out[(size_t)(b * TSZ + rg) * CSZ + gc] = w0;
    *(float2*)&out[(size_t)(b * TSZ + rg + 8) * CSZ + gc] = w1;
  }
}

// ---------------------------------------------------------------------------
extern "C" void kernel_launch(void* const* d_in, const int* in_sizes, int n_in,
                              void* d_out, int out_size) {
  const float* x    = (const float*)d_in[0];
  const float* W    = (const float*)d_in[1];
  const float* bias = (const float*)d_in[2];
  float* out = (float*)d_out;

  (void)in_sizes; (void)n_in; (void)out_size;

  dim3 gp0(32, 56);
  gemm_frag_prep_kernel<<<gp0, 256>>>(x, W);

  cudaFuncSetAttribute(qkv_gemm_mma_kernel,
                       cudaFuncAttributeMaxDynamicSharedMemorySize,
                       GSMEM_TOTAL);
  dim3 g1(NC3 / 128, (BSZ * TSZ) / 128);   // (24, 32)
  qkv_gemm_mma_kernel<<<g1, 256, GSMEM_TOTAL>>>(bias);

  dim3 gp1(48, NH, BSZ);                   // 16 Q tiles + 32 KV tiles
  qkv_frag_prep_kernel<<<gp1, 256>>>();

  cudaFuncSetAttribute(flash_attn_mma_kernel,
                       cudaFuncAttributeMaxDynamicSharedMemorySize, FSMEM);
  dim3 g2(TSZ / FTQ, NH, BSZ);             // (16, 16, 2)
  flash_attn_mma_kernel<<<g2, 256, FSMEM>>>(out);
}

// round 14
// speedup vs baseline: 1.1933x; 1.1933x over previous
#include <cuda_runtime.h>
#include <math.h>
#include <stdint.h>

// Problem constants
#define BSZ   2
#define TSZ   2048
#define CSZ   1024
#define NH    16
#define HSD   64
#define NC3   3072   // 3*C

// Scratch: qkv = x @ W + b   [B, T, 3C]
__device__ float g_qkv[(size_t)BSZ * TSZ * NC3];
// Prebuilt GEMM operand fragment images (tf32 bits)
__device__ uint32_t g_afrag[(size_t)32 * 32 * 4096];   // [m_blk][chunk][16KB]
__device__ uint32_t g_bfrag[(size_t)24 * 32 * 4096];   // [n_blk][chunk][16KB]
// Prebuilt K/V fragment tiles: [b][h][kt:32][32KB image] (K 16KB + V 16KB)
// V token rows permuted by pi(t)=2t / 2t-7 so S-accum == P A-fragment.
__device__ float g_kvfrag[(size_t)BSZ * NH * 32 * 8192];

// Q pre-scale: (1/sqrt(64)) * log2(e)  -> softmax runs in exp2 domain
#define QSCALE 0.18033688011112042f

// ===========================================================================
// helpers
// ===========================================================================
__device__ __forceinline__ uint32_t f2tf32(float f) {
  uint32_t r;
  asm("cvt.rna.tf32.f32 %0, %1;" : "=r"(r) : "f"(f));
  return r;
}
__device__ __forceinline__ float ex2f(float x) {
  float r;
  asm("ex2.approx.f32 %0, %1;" : "=f"(r) : "f"(x));
  return r;
}
__device__ __forceinline__ int uswz(int lane) {
  int q = lane >> 2;
  return (q << 2) | ((lane + q + (q >> 2)) & 3);
}
__device__ __forceinline__ uint32_t smem_u32(const void* p) {
  uint32_t a;
  asm("{ .reg .u64 t; cvta.to.shared.u64 t, %1; cvt.u32.u64 %0, t; }"
      : "=r"(a) : "l"(p));
  return a;
}
#define MMA_TF32(d, a, b)                                                  \
  asm volatile(                                                            \
      "mma.sync.aligned.m16n8k8.row.col.f32.tf32.tf32.f32 "                \
      "{%0,%1,%2,%3}, {%4,%5,%6,%7}, {%8,%9}, {%0,%1,%2,%3};"              \
      : "+f"((d)[0]), "+f"((d)[1]), "+f"((d)[2]), "+f"((d)[3])             \
      : "r"((a).x), "r"((a).y), "r"((a).z), "r"((a).w),                    \
        "r"((b).x), "r"((b).y))
// A operand given as 4 float registers holding tf32 bit patterns.
#define MMA_TF32F(d, a0, a1, a2, a3, b)                                    \
  asm volatile(                                                            \
      "mma.sync.aligned.m16n8k8.row.col.f32.tf32.tf32.f32 "                \
      "{%0,%1,%2,%3}, {%4,%5,%6,%7}, {%8,%9}, {%0,%1,%2,%3};"              \
      : "+f"((d)[0]), "+f"((d)[1]), "+f"((d)[2]), "+f"((d)[3])             \
      : "r"(__float_as_uint(a0)), "r"(__float_as_uint(a1)),                \
        "r"(__float_as_uint(a2)), "r"(__float_as_uint(a3)),                \
        "r"((b).x), "r"((b).y))
#define CP_ASYNC16(dst, src)                                               \
  asm volatile("cp.async.cg.shared.global [%0], [%1], 16;"                 \
               :: "r"(dst), "l"(src))
#define CP_COMMIT() asm volatile("cp.async.commit_group;" ::: "memory")
#define CP_WAIT0()  asm volatile("cp.async.wait_group 0;" ::: "memory")
#define CP_WAIT1()  asm volatile("cp.async.wait_group 1;" ::: "memory")

// ===========================================================================
// Kernel 0: build GEMM operand fragment images from x and W (unchanged).
// ===========================================================================
__global__ __launch_bounds__(256) void gemm_frag_prep_kernel(
    const float* __restrict__ A,
    const float* __restrict__ W) {
  const int tid = threadIdx.x;
  const int c = blockIdx.x;            // k-chunk 0..31
  if (blockIdx.y < 32) {
    const int m0 = blockIdx.y * 128;
    const int k0 = c * 32;
    const int a_tile = tid >> 5;
    const int a_ks   = (tid >> 3) & 3;
    const int a_q    = tid & 7;
    const int perm = (a_q + (a_q >> 2)) & 3;
    const float* ap =
        A + (size_t)(m0 + a_tile * 16 + a_q) * CSZ + k0 + a_ks * 8;
    float4 r0a = *(const float4*)(ap);
    float4 r0b = *(const float4*)(ap + 4);
    float4 r1a = *(const float4*)(ap + 8 * CSZ);
    float4 r1b = *(const float4*)(ap + 8 * CSZ + 4);
    const float r0[8] = {r0a.x, r0a.y, r0a.z, r0a.w, r0b.x, r0b.y, r0b.z, r0b.w};
    const float r1[8] = {r1a.x, r1a.y, r1a.z, r1a.w, r1b.x, r1b.y, r1b.z, r1b.w};
    char* dst = (char*)g_afrag + ((size_t)(blockIdx.y * 32 + c)) * 16384 +
                (a_tile * 4 + a_ks) * 512;
#pragma unroll
    for (int j = 0; j < 4; j++) {
      uint4 v;
      v.x = f2tf32(r0[j]);
      v.y = f2tf32(r1[j]);
      v.z = f2tf32(r0[j + 4]);
      v.w = f2tf32(r1[j + 4]);
      *(uint4*)(dst + (4 * a_q + ((j + perm) & 3)) * 16) = v;
    }
  } else {
    const int n_blk = blockIdx.y - 32;
    const int n0 = n_blk * 128;
    const int k0 = c * 32;
#pragma unroll
    for (int i = 0; i < 2; i++) {
      const int u = tid + i * 256;
      const int nh = u & 1;
      const int kk = (u >> 1) & 3;
      const int ks = (u >> 3) & 3;
      const int nt = u >> 5;
      const float* bp = W + (size_t)(k0 + ks * 8 + kk) * NC3 + n0 +
                        nt * 8 + nh * 4;
      float4 b0 = *(const float4*)(bp);
      float4 b1 = *(const float4*)(bp + 4 * NC3);
      const float f0[4] = {b0.x, b0.y, b0.z, b0.w};
      const float f1[4] = {b1.x, b1.y, b1.z, b1.w};
      char* dst = (char*)g_bfrag + ((size_t)(n_blk * 32 + c)) * 16384 +
                  (nt * 4 + ks) * 256;
#pragma unroll
      for (int j = 0; j < 4; j++) {
        const int q = nh * 4 + j;
        const int slot = 4 * q + ((kk + q + (q >> 2)) & 3);
        uint2 v;
        v.x = f2tf32(f0[j]);
        v.y = f2tf32(f1[j]);
        *(uint2*)(dst + slot * 8) = v;
      }
    }
  }
}

// ===========================================================================
// Kernel 1: QKV GEMM from prebuilt fragments (coalesced f32 epilogue).
// ===========================================================================
#define GCHUNK 32768
#define GSMEM_TOTAL (3 * GCHUNK)
#define NCHUNK 32

__global__ __launch_bounds__(256, 2) void qkv_gemm_mma_kernel(
    const float* __restrict__ bias) {
  extern __shared__ char smem[];
  const uint32_t sb = smem_u32(smem);
  const int tid  = threadIdx.x;
  const int lane = tid & 31;
  const int warp = tid >> 5;
  const int wm = warp >> 2;
  const int wn = warp & 3;
  const int m0 = blockIdx.y * 128;
  const int n0 = blockIdx.x * 128;

  const char* asrc0 =
      (const char*)g_afrag + ((size_t)blockIdx.y * 32) * 16384;
  const char* bsrc0 =
      (const char*)g_bfrag + ((size_t)blockIdx.x * 32) * 16384;

  const int rl16 = uswz(lane) * 16;
  const int rl8  = uswz(lane) * 8;

  float acc[4][4][4] = {};

#pragma unroll
  for (int i = 0; i < 4; i++) {
    const int off = tid * 16 + i * 4096;
    CP_ASYNC16(sb + off, asrc0 + off);
    CP_ASYNC16(sb + 16384 + off, bsrc0 + off);
  }
  CP_COMMIT();

  for (int c = 0; c < NCHUNK; c++) {
    if (c + 1 < NCHUNK) {
      const uint32_t dst = sb + ((c + 1) % 3) * GCHUNK;
      const char* as = asrc0 + (size_t)(c + 1) * 16384;
      const char* bs = bsrc0 + (size_t)(c + 1) * 16384;
#pragma unroll
      for (int i = 0; i < 4; i++) {
        const int off = tid * 16 + i * 4096;
        CP_ASYNC16(dst + off, as + off);
        CP_ASYNC16(dst + 16384 + off, bs + off);
      }
      CP_COMMIT();
      CP_WAIT1();
    } else {
      CP_WAIT0();
    }
    __syncthreads();

    const char* ab = smem + (c % 3) * GCHUNK;
    const char* bb = ab + 16384;
#pragma unroll
    for (int ks = 0; ks < 4; ks++) {
      uint4 af[4];
      uint2 bf[4];
#pragma unroll
      for (int mi = 0; mi < 4; mi++)
        af[mi] = *(const uint4*)(ab + ((wm * 4 + mi) * 4 + ks) * 512 + rl16);
#pragma unroll
      for (int ni = 0; ni < 4; ni++)
        bf[ni] = *(const uint2*)(bb + ((wn * 4 + ni) * 4 + ks) * 256 + rl8);
#pragma unroll
      for (int mi = 0; mi < 4; mi++)
#pragma unroll
        for (int ni = 0; ni < 4; ni++)
          MMA_TF32(acc[mi][ni], af[mi], bf[ni]);
    }
  }

  // epilogue: acc + bias -> g_qkv  (coalesced float2 stores)
  const int r_base = m0 + wm * 64 + (lane >> 2);
  const int c_base = n0 + wn * 32 + 2 * (lane & 3);
#pragma unroll
  for (int ni = 0; ni < 4; ni++) {
    const int gc = c_base + ni * 8;
    float2 bv = *(const float2*)&bias[gc];
#pragma unroll
    for (int mi = 0; mi < 4; mi++) {
      const int gr = r_base + mi * 16;
      float2 o0 = make_float2(acc[mi][ni][0] + bv.x, acc[mi][ni][1] + bv.y);
      float2 o1 = make_float2(acc[mi][ni][2] + bv.x, acc[mi][ni][3] + bv.y);
      *(float2*)&g_qkv[(size_t)gr * NC3 + gc] = o0;
      *(float2*)&g_qkv[(size_t)(gr + 8) * NC3 + gc] = o1;
    }
  }
}

// ===========================================================================
// Kernel 1.5: build K/V fragment images once per (b,h,kt)  (R7/R11 version;
// V token rows permuted within each 8-group: token j2 -> logical slot
// jp = ((j2&1)<<2)|(j2>>1), so S-accumulator feeds PV without shuffles).
// ===========================================================================
__global__ __launch_bounds__(256) void kv_frag_prep_kernel() {
  __shared__ char psm[32768];
  const int tid = threadIdx.x;
  const int kt = blockIdx.x;
  const int h  = blockIdx.y;
  const int b  = blockIdx.z;
  const int k0 = kt * 64;
  const float* qkv = g_qkv;

#pragma unroll
  for (int i = 0; i < 2; i++) {
    const int u = tid + i * 256;
    const int g = u >> 3;
    {
      const int q = u & 7;
      const float* kp = qkv +
          (size_t)(b * TSZ + k0 + (u >> 6) * 8 + q) * NC3 + CSZ +
          h * HSD + ((u >> 3) & 7) * 8;
      float4 ka = *(const float4*)(kp);
      float4 kb = *(const float4*)(kp + 4);
      char* p = psm + g * 256 + ((q ^ (g & 7)) * 32);
      uint4 w0, w1;
      w0.x = f2tf32(ka.x); w0.y = f2tf32(kb.x);
      w0.z = f2tf32(ka.y); w0.w = f2tf32(kb.y);
      w1.x = f2tf32(ka.z); w1.y = f2tf32(kb.z);
      w1.z = f2tf32(ka.w); w1.w = f2tf32(kb.w);
      ((uint4*)p)[0] = w0;
      ((uint4*)p)[1] = w1;
    }
    {
      const int j2 = u & 7;                         // actual token in 8-group
      const int jp = ((j2 & 1) << 2) | (j2 >> 1);   // logical k-slot
      const float* vp = qkv +
          (size_t)(b * TSZ + k0 + ((u >> 3) & 7) * 8 + j2) * NC3 +
          2 * CSZ + h * HSD + (u >> 6) * 8;
      float4 va = *(const float4*)(vp);
      float4 vb = *(const float4*)(vp + 4);
      const float vv[8] = {va.x, va.y, va.z, va.w, vb.x, vb.y, vb.z, vb.w};
      char* base = psm + 16384 + g * 256 + (jp & 3) * 8 + (jp >> 2) * 4;
#pragma unroll
      for (int q = 0; q < 8; q++) {
        *(uint32_t*)(base + ((q ^ (g & 7)) * 32)) = f2tf32(vv[q]);
      }
    }
  }
  __syncthreads();

  float4* dst = (float4*)(g_kvfrag + ((size_t)((b * NH + h) * 32 + kt)) * 8192);
  const float4* src = (const float4*)psm;
#pragma unroll
  for (int i = 0; i < 8; i++) {
    const int c = tid + i * 256;
    dst[c] = src[c];
  }
}

// ===========================================================================
// Kernel 2: flash attention (R11 structure; P fragment built IN PLACE from
// the S accumulator via element permutation — zero shuffles, no pf array).
// ===========================================================================
#define FTQ 128
#define FTK 64
#define FBUF0 32768
#define FSMEM (96 * 1024)

__global__ __launch_bounds__(256, 2) void flash_attn_mma_kernel(
    float* __restrict__ out) {
  extern __shared__ char fsm[];
  const uint32_t sb = smem_u32(fsm);
  const int tid  = threadIdx.x;
  const int lane = tid & 31;
  const int warp = tid >> 5;
  const int qt = gridDim.x - 1 - blockIdx.x;   // heavy tiles first
  const int h  = blockIdx.y;
  const int b  = blockIdx.z;
  const int q0 = qt * FTQ;
  const float* qkv = g_qkv;
  const float* tiles = g_kvfrag + ((size_t)((b * NH + h) * 32)) * 8192;

  // ---- build Q fragments once (A-frag layout, scaled by QSCALE) ----
#pragma unroll
  for (int i = 0; i < 2; i++) {
    const int u = tid + i * 256;
    const int wt = u >> 6, ks = (u >> 3) & 7, q = u & 7;
    const float* qp =
        qkv + (size_t)(b * TSZ + q0 + wt * 16 + q) * NC3 + h * HSD + ks * 8;
    float4 r0a = *(const float4*)(qp);
    float4 r0b = *(const float4*)(qp + 4);
    float4 r1a = *(const float4*)(qp + (size_t)8 * NC3);
    float4 r1b = *(const float4*)(qp + (size_t)8 * NC3 + 4);
    const float r0[8] = {r0a.x, r0a.y, r0a.z, r0a.w, r0b.x, r0b.y, r0b.z, r0b.w};
    const float r1[8] = {r1a.x, r1a.y, r1a.z, r1a.w, r1b.x, r1b.y, r1b.z, r1b.w};
    const int perm = (q + (q >> 2)) & 3;
    char* gb = fsm + (wt * 8 + ks) * 512;
#pragma unroll
    for (int j = 0; j < 4; j++) {
      uint4 v;
      v.x = f2tf32(r0[j] * QSCALE);
      v.y = f2tf32(r1[j] * QSCALE);
      v.z = f2tf32(r0[j + 4] * QSCALE);
      v.w = f2tf32(r1[j + 4] * QSCALE);
      *(uint4*)(gb + (4 * q + ((j + perm) & 3)) * 16) = v;
    }
  }

  // ---- prologue: async-copy tile 0 ----
#pragma unroll
  for (int i = 0; i < 8; i++) {
    const int c = tid + i * 256;
    CP_ASYNC16(sb + FBUF0 + c * 16, (const char*)tiles + c * 16);
  }
  CP_COMMIT();
  CP_WAIT0();
  __syncthreads();   // Q frags + tile 0 visible

  float m0 = -1e30f, m1 = -1e30f, l0 = 0.f, l1 = 0.f;
  float o[8][4] = {};
  const int wrow0 = q0 + warp * 16;
  const int qrl16 = uswz(lane) * 16;
  const int last_kt = 2 * qt + 1;

  for (int kt = 0; kt <= last_kt; kt++) {
    const int cur = kt & 1;

    if (kt < last_kt) {
      const char* src = (const char*)(tiles + (size_t)(kt + 1) * 8192);
      const uint32_t dst = sb + FBUF0 + (1 - cur) * 32768;
#pragma unroll
      for (int i = 0; i < 8; i++) {
        const int c = tid + i * 256;
        CP_ASYNC16(dst + c * 16, src + c * 16);
      }
      CP_COMMIT();
    }

    const int k0 = kt * FTK;
    if (k0 <= wrow0 + 15) {
      const char* kf = fsm + FBUF0 + cur * 32768;
      const char* vf = kf + 16384;

      // ---- S = Q K^T ----
      float s[8][4];
#pragma unroll
      for (int nt = 0; nt < 8; nt++)
        s[nt][0] = s[nt][1] = s[nt][2] = s[nt][3] = 0.f;
#pragma unroll
      for (int ks = 0; ks < 8; ks++) {
        uint4 qf = *(const uint4*)(fsm + (warp * 8 + ks) * 512 + qrl16);
#pragma unroll
        for (int nt = 0; nt < 8; nt++) {
          const int g = nt * 8 + ks;
          uint2 kfr = *(const uint2*)(kf + g * 256 +
                                      (((lane >> 2) ^ (g & 7)) * 32) +
                                      (lane & 3) * 8);
          MMA_TF32(s[nt], qf, kfr);
        }
      }

      // ---- causal mask ----
      const int r0g = wrow0 + (lane >> 2);
      const int r1g = r0g + 8;
      const int lr2 = 2 * (lane & 3);
      if (k0 + FTK - 1 > wrow0) {
#pragma unroll
        for (int nt = 0; nt < 8; nt++) {
          const int cg = k0 + nt * 8 + lr2;
          if (cg     > r0g) s[nt][0] = -1e30f;
          if (cg + 1 > r0g) s[nt][1] = -1e30f;
          if (cg     > r1g) s[nt][2] = -1e30f;
          if (cg + 1 > r1g) s[nt][3] = -1e30f;
        }
      }

      // ---- online softmax in exp2 domain (register, quad-reduced) ----
      float mx0 = -1e30f, mx1 = -1e30f;
#pragma unroll
      for (int nt = 0; nt < 8; nt++) {
        mx0 = fmaxf(mx0, fmaxf(s[nt][0], s[nt][1]));
        mx1 = fmaxf(mx1, fmaxf(s[nt][2], s[nt][3]));
      }
      mx0 = fmaxf(mx0, __shfl_xor_sync(0xffffffffu, mx0, 1));
      mx0 = fmaxf(mx0, __shfl_xor_sync(0xffffffffu, mx0, 2));
      mx1 = fmaxf(mx1, __shfl_xor_sync(0xffffffffu, mx1, 1));
      mx1 = fmaxf(mx1, __shfl_xor_sync(0xffffffffu, mx1, 2));
      const float mn0 = fmaxf(m0, mx0);
      const float mn1 = fmaxf(m1, mx1);
      const float al0 = ex2f(m0 - mn0);
      const float al1 = ex2f(m1 - mn1);
      float sum0 = 0.f, sum1 = 0.f;
#pragma unroll
      for (int nt = 0; nt < 8; nt++) {
        s[nt][0] = ex2f(s[nt][0] - mn0); sum0 += s[nt][0];
        s[nt][1] = ex2f(s[nt][1] - mn0); sum0 += s[nt][1];
        s[nt][2] = ex2f(s[nt][2] - mn1); sum1 += s[nt][2];
        s[nt][3] = ex2f(s[nt][3] - mn1); sum1 += s[nt][3];
      }
      sum0 += __shfl_xor_sync(0xffffffffu, sum0, 1);
      sum0 += __shfl_xor_sync(0xffffffffu, sum0, 2);
      sum1 += __shfl_xor_sync(0xffffffffu, sum1, 1);
      sum1 += __shfl_xor_sync(0xffffffffu, sum1, 2);
      m0 = mn0; m1 = mn1;
      l0 = l0 * al0 + sum0;
      l1 = l1 * al1 + sum1;

      // ---- P fragment IN PLACE: {a0,a1,a2,a3} = {c0,c2,c1,c3} (tf32) ----
      // (V rows were permuted in prep so this is the exact A-fragment.)
#pragma unroll
      for (int ks = 0; ks < 8; ks++) {
        float t0 = __uint_as_float(f2tf32(s[ks][0]));
        float t1 = __uint_as_float(f2tf32(s[ks][2]));
        float t2 = __uint_as_float(f2tf32(s[ks][1]));
        float t3 = __uint_as_float(f2tf32(s[ks][3]));
        s[ks][0] = t0; s[ks][1] = t1; s[ks][2] = t2; s[ks][3] = t3;
      }

      // ---- O = O*alpha + P V ----
#pragma unroll
      for (int nt = 0; nt < 8; nt++) {
        o[nt][0] *= al0; o[nt][1] *= al0;
        o[nt][2] *= al1; o[nt][3] *= al1;
      }
#pragma unroll
      for (int nd = 0; nd < 8; nd++) {
#pragma unroll
        for (int ks = 0; ks < 8; ks++) {
          const int g = nd * 8 + ks;
          uint2 vfr = *(const uint2*)(vf + g * 256 +
                                      (((lane >> 2) ^ (g & 7)) * 32) +
                                      (lane & 3) * 8);
          MMA_TF32F(o[nd], s[ks][0], s[ks][1], s[ks][2], s[ks][3], vfr);
        }
      }
    }

    CP_WAIT0();       // next tile's copy done (overlapped with compute)
    __syncthreads();  // single barrier per tile
  }

  // ---- epilogue: normalize, write out[b, q, h*64 + d] ----
  const float i0 = 1.f / l0;
  const float i1 = 1.f / l1;
  const int r0g = q0 + warp * 16 + (lane >> 2);
  const int lr2 = 2 * (lane & 3);
#pragma unroll
  for (int nd = 0; nd < 8; nd++) {
    const int gc = h * HSD + nd * 8 + lr2;
    float2 w0 = make_float2(o[nd][0] * i0, o[nd][1] * i0);
    float2 w1 = make_float2(o[nd][2] * i1, o[nd][3] * i1);
    *(float2*)&out[(size_t)(b * TSZ + r0g) * CSZ + gc] = w0;
    *(float2*)&out[(size_t)(b * TSZ + r0g + 8) * CSZ + gc] = w1;
  }
}

// ---------------------------------------------------------------------------
extern "C" void kernel_launch(void* const* d_in, const int* in_sizes, int n_in,
                              void* d_out, int out_size) {
  const float* x    = (const float*)d_in[0];
  const float* W    = (const float*)d_in[1];
  const float* bias = (const float*)d_in[2];
  float* out = (float*)d_out;

  (void)in_sizes; (void)n_in; (void)out_size;

  dim3 gp0(32, 56);
  gemm_frag_prep_kernel<<<gp0, 256>>>(x, W);

  cudaFuncSetAttribute(qkv_gemm_mma_kernel,
                       cudaFuncAttributeMaxDynamicSharedMemorySize,
                       GSMEM_TOTAL);
  dim3 g1(NC3 / 128, (BSZ * TSZ) / 128);   // (24, 32)
  qkv_gemm_mma_kernel<<<g1, 256, GSMEM_TOTAL>>>(bias);

  dim3 gp(32, NH, BSZ);                    // (32, 16, 2)
  kv_frag_prep_kernel<<<gp, 256>>>();

  cudaFuncSetAttribute(flash_attn_mma_kernel,
                       cudaFuncAttributeMaxDynamicSharedMemorySize, FSMEM);
  dim3 g2(TSZ / FTQ, NH, BSZ);             // (16, 16, 2)
  flash_attn_mma_kernel<<<g2, 256, FSMEM>>>(out);
}

// round 15
// speedup vs baseline: 1.9500x; 1.6341x over previous
#include <cuda_runtime.h>
#include <math.h>
#include <stdint.h>

// Problem constants
#define BSZ   2
#define TSZ   2048
#define CSZ   1024
#define NH    16
#define HSD   64
#define NC3   3072   // 3*C

// Scratch: qkv = x @ W + b   [B, T, 3C]  (f32)
__device__ float g_qkv[(size_t)BSZ * TSZ * NC3];
// fp16 fragment images (packed half2 words)
__device__ uint32_t g_afrag[(size_t)32 * 32 * 2048];   // [m_blk][chunk][8KB]
__device__ uint32_t g_bfrag[(size_t)24 * 32 * 2048];   // [n_blk][chunk][8KB]
__device__ uint32_t g_qfrag[(size_t)BSZ * NH * 16 * 4096];   // [b][h][qt][16KB]
__device__ uint32_t g_kvfrag[(size_t)BSZ * NH * 32 * 4096];  // [b][h][kt][K8K+V8K]

// Q pre-scale: (1/sqrt(64)) * log2(e)  -> softmax in exp2 domain
#define QSCALE 0.18033688011112042f

// ===========================================================================
// helpers
// ===========================================================================
__device__ __forceinline__ float ex2f(float x) {
  float r;
  asm("ex2.approx.f32 %0, %1;" : "=f"(r) : "f"(x));
  return r;
}
__device__ __forceinline__ uint32_t smem_u32(const void* p) {
  uint32_t a;
  asm("{ .reg .u64 t; cvta.to.shared.u64 t, %1; cvt.u32.u64 %0, t; }"
      : "=r"(a) : "l"(p));
  return a;
}
// pack two f32 -> f16x2 (lo = first arg, hi = second)
__device__ __forceinline__ uint32_t f16x2(float lo, float hi) {
  uint32_t r;
  asm("cvt.rn.f16x2.f32 %0, %1, %2;" : "=r"(r) : "f"(hi), "f"(lo));
  return r;
}
#define MMA_F16(d, a0, a1, a2, a3, b)                                      \
  asm volatile(                                                            \
      "mma.sync.aligned.m16n8k16.row.col.f32.f16.f16.f32 "                 \
      "{%0,%1,%2,%3}, {%4,%5,%6,%7}, {%8,%9}, {%0,%1,%2,%3};"              \
      : "+f"((d)[0]), "+f"((d)[1]), "+f"((d)[2]), "+f"((d)[3])             \
      : "r"(a0), "r"(a1), "r"(a2), "r"(a3), "r"((b).x), "r"((b).y))
#define MMA_F16V(d, av, b)                                                 \
  MMA_F16(d, (av).x, (av).y, (av).z, (av).w, b)
#define CP_ASYNC16(dst, src)                                               \
  asm volatile("cp.async.cg.shared.global [%0], [%1], 16;"                 \
               :: "r"(dst), "l"(src))
#define CP_COMMIT() asm volatile("cp.async.commit_group;" ::: "memory")
#define CP_WAIT0()  asm volatile("cp.async.wait_group 0;" ::: "memory")
#define CP_WAIT1()  asm volatile("cp.async.wait_group 1;" ::: "memory")

// ===========================================================================
// Kernel 0: build fp16 GEMM operand fragment images from x and W.
// grid (32 chunks, 56): y<32 -> A frags (m_blk=y); y>=32 -> B frags.
// A group g = tile*2+ks16 (16 groups x 512B); B group g = ntile*2+ks16
// (32 groups x 256B).  All stores coalesced.
// ===========================================================================
__global__ __launch_bounds__(256) void gemm_frag_prep_kernel(
    const float* __restrict__ A,
    const float* __restrict__ W) {
  const int tid = threadIdx.x;
  const int c = blockIdx.x;            // k-chunk 0..31 (32 floats each)
  const int k0 = c * 32;
  if (blockIdx.y < 32) {
    const int m0 = blockIdx.y * 128;
    char* img = (char*)g_afrag + ((size_t)(blockIdx.y * 32 + c)) * 8192;
#pragma unroll
    for (int i = 0; i < 2; i++) {
      const int u = tid + i * 256;       // 512 units
      const int g = u >> 5, lane = u & 31;
      const int tile = g >> 1, ks = g & 1;
      const int r = lane >> 2, t = lane & 3;
      const float* ap = A + (size_t)(m0 + tile * 16 + r) * CSZ + k0 + ks * 16;
      float2 p00 = *(const float2*)(ap + 2 * t);
      float2 p01 = *(const float2*)(ap + 2 * t + 8);
      float2 p10 = *(const float2*)(ap + 8 * CSZ + 2 * t);
      float2 p11 = *(const float2*)(ap + 8 * CSZ + 2 * t + 8);
      uint4 v;
      v.x = f16x2(p00.x, p00.y);
      v.y = f16x2(p10.x, p10.y);
      v.z = f16x2(p01.x, p01.y);
      v.w = f16x2(p11.x, p11.y);
      *(uint4*)(img + g * 512 + lane * 16) = v;
    }
  } else {
    const int n_blk = blockIdx.y - 32;
    const int n0 = n_blk * 128;
    char* img = (char*)g_bfrag + ((size_t)(n_blk * 32 + c)) * 8192;
#pragma unroll
    for (int i = 0; i < 4; i++) {
      const int u = tid + i * 256;       // 1024 units
      const int g = u >> 5, lane = u & 31;
      const int ntile = g >> 1, ks = g & 1;
      const int gq = lane >> 2, t = lane & 3;
      const int n = n0 + ntile * 8 + gq;
      const float* wp = W + (size_t)(k0 + ks * 16 + 2 * t) * NC3 + n;
      float w0 = wp[0];
      float w1 = wp[NC3];
      float w2 = wp[(size_t)8 * NC3];
      float w3 = wp[(size_t)9 * NC3];
      uint2 v;
      v.x = f16x2(w0, w1);
      v.y = f16x2(w2, w3);
      *(uint2*)(img + g * 256 + lane * 8) = v;
    }
  }
}

// ===========================================================================
// Kernel 1: QKV GEMM from fp16 fragments.  CTA 128x128, K-chunk 32
// (2 k16 steps), triple-buffered cp.async, 16KB/chunk.  Smem 48KB.
// ===========================================================================
#define GCHUNK 16384
#define GSMEM_TOTAL (3 * GCHUNK)
#define NCHUNK 32

__global__ __launch_bounds__(256, 2) void qkv_gemm_mma_kernel(
    const float* __restrict__ bias) {
  extern __shared__ char smem[];
  const uint32_t sb = smem_u32(smem);
  const int tid  = threadIdx.x;
  const int lane = tid & 31;
  const int warp = tid >> 5;
  const int wm = warp >> 2;
  const int wn = warp & 3;
  const int m0 = blockIdx.y * 128;
  const int n0 = blockIdx.x * 128;

  const char* asrc0 = (const char*)g_afrag + ((size_t)blockIdx.y * 32) * 8192;
  const char* bsrc0 = (const char*)g_bfrag + ((size_t)blockIdx.x * 32) * 8192;

  float acc[4][4][4] = {};

  // prologue: chunk 0 -> buf 0
#pragma unroll
  for (int i = 0; i < 2; i++) {
    const int off = tid * 16 + i * 4096;
    CP_ASYNC16(sb + off, asrc0 + off);
    CP_ASYNC16(sb + 8192 + off, bsrc0 + off);
  }
  CP_COMMIT();

  for (int c = 0; c < NCHUNK; c++) {
    if (c + 1 < NCHUNK) {
      const uint32_t dst = sb + ((c + 1) % 3) * GCHUNK;
      const char* as = asrc0 + (size_t)(c + 1) * 8192;
      const char* bs = bsrc0 + (size_t)(c + 1) * 8192;
#pragma unroll
      for (int i = 0; i < 2; i++) {
        const int off = tid * 16 + i * 4096;
        CP_ASYNC16(dst + off, as + off);
        CP_ASYNC16(dst + 8192 + off, bs + off);
      }
      CP_COMMIT();
      CP_WAIT1();
    } else {
      CP_WAIT0();
    }
    __syncthreads();

    const char* ab = smem + (c % 3) * GCHUNK;
    const char* bb = ab + 8192;
#pragma unroll
    for (int ks = 0; ks < 2; ks++) {
      uint4 af[4];
      uint2 bf[4];
#pragma unroll
      for (int mi = 0; mi < 4; mi++)
        af[mi] = *(const uint4*)(ab + (((wm * 4 + mi) * 2 + ks) * 512) +
                                 lane * 16);
#pragma unroll
      for (int ni = 0; ni < 4; ni++)
        bf[ni] = *(const uint2*)(bb + (((wn * 4 + ni) * 2 + ks) * 256) +
                                 lane * 8);
#pragma unroll
      for (int mi = 0; mi < 4; mi++)
#pragma unroll
        for (int ni = 0; ni < 4; ni++)
          MMA_F16V(acc[mi][ni], af[mi], bf[ni]);
    }
  }

  // epilogue: acc + bias -> g_qkv  (coalesced float2 stores)
  const int r_base = m0 + wm * 64 + (lane >> 2);
  const int c_base = n0 + wn * 32 + 2 * (lane & 3);
#pragma unroll
  for (int ni = 0; ni < 4; ni++) {
    const int gc = c_base + ni * 8;
    float2 bv = *(const float2*)&bias[gc];
#pragma unroll
    for (int mi = 0; mi < 4; mi++) {
      const int gr = r_base + mi * 16;
      float2 o0 = make_float2(acc[mi][ni][0] + bv.x, acc[mi][ni][1] + bv.y);
      float2 o1 = make_float2(acc[mi][ni][2] + bv.x, acc[mi][ni][3] + bv.y);
      *(float2*)&g_qkv[(size_t)gr * NC3 + gc] = o0;
      *(float2*)&g_qkv[(size_t)(gr + 8) * NC3 + gc] = o1;
    }
  }
}

// ===========================================================================
// Kernel 1.5: build fp16 Q / K / V fragment images from g_qkv.
// Grid (48, 16, 2): x<16 -> Q tile qt=x (16KB); x>=16 -> KV tile (8K+8K).
// ===========================================================================
__global__ __launch_bounds__(256) void qkv_frag_prep_kernel() {
  const int tid = threadIdx.x;
  const int h = blockIdx.y;
  const int b = blockIdx.z;
  const float* qkv = g_qkv;

  if (blockIdx.x < 16) {
    const int qt = blockIdx.x;
    const int q0 = qt * 128;
    char* qimg = (char*)g_qfrag + ((size_t)((b * NH + h) * 16 + qt)) * 16384;
#pragma unroll
    for (int i = 0; i < 4; i++) {
      const int u = tid + i * 256;       // 1024 units
      const int g = u >> 5, lane = u & 31;
      const int wt = g >> 2, ks = g & 3;
      const int r = lane >> 2, t = lane & 3;
      const float* qp = qkv + (size_t)(b * TSZ + q0 + wt * 16 + r) * NC3 +
                        h * HSD + ks * 16;
      float2 p00 = *(const float2*)(qp + 2 * t);
      float2 p01 = *(const float2*)(qp + 2 * t + 8);
      float2 p10 = *(const float2*)(qp + (size_t)8 * NC3 + 2 * t);
      float2 p11 = *(const float2*)(qp + (size_t)8 * NC3 + 2 * t + 8);
      uint4 v;
      v.x = f16x2(p00.x * QSCALE, p00.y * QSCALE);
      v.y = f16x2(p10.x * QSCALE, p10.y * QSCALE);
      v.z = f16x2(p01.x * QSCALE, p01.y * QSCALE);
      v.w = f16x2(p11.x * QSCALE, p11.y * QSCALE);
      *(uint4*)(qimg + g * 512 + lane * 16) = v;
    }
  } else {
    const int kt = blockIdx.x - 16;
    const int k0 = kt * 64;
    char* kvimg = (char*)g_kvfrag + ((size_t)((b * NH + h) * 32 + kt)) * 16384;

    // K: B-frag groups g = nt*4 + ks (8 token-octets x 4 d-ksteps)
#pragma unroll
    for (int i = 0; i < 4; i++) {
      const int u = tid + i * 256;       // 1024 units
      const int g = u >> 5, lane = u & 31;
      const int nt = g >> 2, ks = g & 3;
      const int t = lane & 3;
      const float* kp = qkv +
          (size_t)(b * TSZ + k0 + nt * 8 + (lane >> 2)) * NC3 + CSZ +
          h * HSD + ks * 16;
      float2 ka = *(const float2*)(kp + 2 * t);
      float2 kb = *(const float2*)(kp + 2 * t + 8);
      uint2 v;
      v.x = f16x2(ka.x, ka.y);
      v.y = f16x2(kb.x, kb.y);
      *(uint2*)(kvimg + g * 256 + lane * 8) = v;
    }

    // V: B-frag groups g = nd*4 + kg (8 d-octets x 4 token-k16 groups)
#pragma unroll
    for (int i = 0; i < 4; i++) {
      const int u = tid + i * 256;       // 1024 units
      const int g = u >> 5, lane = u & 31;
      const int nd = g >> 2, kg = g & 3;
      const int t = lane & 3;
      const int d = nd * 8 + (lane >> 2);
      const size_t base = (size_t)(b * TSZ + k0 + kg * 16) * NC3 +
                          2 * CSZ + h * HSD + d;
      float v0 = qkv[base + (size_t)(2 * t) * NC3];
      float v1 = qkv[base + (size_t)(2 * t + 1) * NC3];
      float v2 = qkv[base + (size_t)(2 * t + 8) * NC3];
      float v3 = qkv[base + (size_t)(2 * t + 9) * NC3];
      uint2 v;
      v.x = f16x2(v0, v1);
      v.y = f16x2(v2, v3);
      *(uint2*)(kvimg + 8192 + g * 256 + lane * 8) = v;
    }
  }
}

// ===========================================================================
// Kernel 2: flash attention on fp16 m16n8k16.  TQ=128 (8 warps x 16 rows),
// TK=64.  S: 32 MMAs/tile/thread; PV: 32.  P fragment = packed S accum
// (native layout, zero shuffles).  Smem: Q 16KB + 2x16KB KV = 48KB.
// ===========================================================================
#define FTQ 128
#define FTK 64
#define FBUF0 16384
#define FSMEM (48 * 1024)

__global__ __launch_bounds__(256, 2) void flash_attn_mma_kernel(
    float* __restrict__ out) {
  extern __shared__ char fsm[];
  const uint32_t sb = smem_u32(fsm);
  const int tid  = threadIdx.x;
  const int lane = tid & 31;
  const int warp = tid >> 5;
  const int qt = gridDim.x - 1 - blockIdx.x;   // heavy tiles first
  const int h  = blockIdx.y;
  const int b  = blockIdx.z;
  const int q0 = qt * FTQ;
  const char* qimg =
      (const char*)g_qfrag + ((size_t)((b * NH + h) * 16 + qt)) * 16384;
  const char* tiles =
      (const char*)g_kvfrag + ((size_t)((b * NH + h) * 32)) * 16384;

  // prologue: Q image + KV tile 0
#pragma unroll
  for (int i = 0; i < 4; i++) {
    const int c = (tid + i * 256) * 16;
    CP_ASYNC16(sb + c, qimg + c);
    CP_ASYNC16(sb + FBUF0 + c, tiles + c);
  }
  CP_COMMIT();
  CP_WAIT0();
  __syncthreads();

  float m0 = -1e30f, m1 = -1e30f, l0 = 0.f, l1 = 0.f;
  float o[8][4] = {};
  const int wrow0 = q0 + warp * 16;
  const int r0g = wrow0 + (lane >> 2);
  const int r1g = r0g + 8;
  const int lr2 = 2 * (lane & 3);
  const int last_kt = 2 * qt + 1;

  for (int kt = 0; kt <= last_kt; kt++) {
    const int cur = kt & 1;

    if (kt < last_kt) {
      const char* src = tiles + (size_t)(kt + 1) * 16384;
      const uint32_t dst = sb + FBUF0 + (1 - cur) * 16384;
#pragma unroll
      for (int i = 0; i < 4; i++) {
        const int c = (tid + i * 256) * 16;
        CP_ASYNC16(dst + c, src + c);
      }
      CP_COMMIT();
    }

    const int k0 = kt * FTK;
    if (k0 <= wrow0 + 15) {
      const char* kf = fsm + FBUF0 + cur * 16384;
      const char* vf = kf + 8192;

      // ---- S = Q K^T  (4 k16-steps x 8 token-octets) ----
      float s[8][4];
#pragma unroll
      for (int nt = 0; nt < 8; nt++)
        s[nt][0] = s[nt][1] = s[nt][2] = s[nt][3] = 0.f;
#pragma unroll
      for (int ks = 0; ks < 4; ks++) {
        uint4 qf = *(const uint4*)(fsm + (warp * 4 + ks) * 512 + lane * 16);
#pragma unroll
        for (int nt = 0; nt < 8; nt++) {
          uint2 kfr = *(const uint2*)(kf + (nt * 4 + ks) * 256 + lane * 8);
          MMA_F16V(s[nt], qf, kfr);
        }
      }

      // ---- causal mask ----
      if (k0 + FTK - 1 > wrow0) {
#pragma unroll
        for (int nt = 0; nt < 8; nt++) {
          const int cg = k0 + nt * 8 + lr2;
          if (cg     > r0g) s[nt][0] = -1e30f;
          if (cg + 1 > r0g) s[nt][1] = -1e30f;
          if (cg     > r1g) s[nt][2] = -1e30f;
          if (cg + 1 > r1g) s[nt][3] = -1e30f;
        }
      }

      // ---- online softmax in exp2 domain (register, quad-reduced) ----
      float mx0 = -1e30f, mx1 = -1e30f;
#pragma unroll
      for (int nt = 0; nt < 8; nt++) {
        mx0 = fmaxf(mx0, fmaxf(s[nt][0], s[nt][1]));
        mx1 = fmaxf(mx1, fmaxf(s[nt][2], s[nt][3]));
      }
      mx0 = fmaxf(mx0, __shfl_xor_sync(0xffffffffu, mx0, 1));
      mx0 = fmaxf(mx0, __shfl_xor_sync(0xffffffffu, mx0, 2));
      mx1 = fmaxf(mx1, __shfl_xor_sync(0xffffffffu, mx1, 1));
      mx1 = fmaxf(mx1, __shfl_xor_sync(0xffffffffu, mx1, 2));
      const float mn0 = fmaxf(m0, mx0);
      const float mn1 = fmaxf(m1, mx1);
      const float al0 = ex2f(m0 - mn0);
      const float al1 = ex2f(m1 - mn1);
      float sum0 = 0.f, sum1 = 0.f;
#pragma unroll
      for (int nt = 0; nt < 8; nt++) {
        s[nt][0] = ex2f(s[nt][0] - mn0); sum0 += s[nt][0];
        s[nt][1] = ex2f(s[nt][1] - mn0); sum0 += s[nt][1];
        s[nt][2] = ex2f(s[nt][2] - mn1); sum1 += s[nt][2];
        s[nt][3] = ex2f(s[nt][3] - mn1); sum1 += s[nt][3];
      }
      sum0 += __shfl_xor_sync(0xffffffffu, sum0, 1);
      sum0 += __shfl_xor_sync(0xffffffffu, sum0, 2);
      sum1 += __shfl_xor_sync(0xffffffffu, sum1, 1);
      sum1 += __shfl_xor_sync(0xffffffffu, sum1, 2);
      m0 = mn0; m1 = mn1;
      l0 = l0 * al0 + sum0;
      l1 = l1 * al1 + sum1;

      // ---- O = O*alpha + P V  (P = packed S accum, native fp16 A-frag) ----
#pragma unroll
      for (int nt = 0; nt < 8; nt++) {
        o[nt][0] *= al0; o[nt][1] *= al0;
        o[nt][2] *= al1; o[nt][3] *= al1;
      }
#pragma unroll
      for (int kg = 0; kg < 4; kg++) {
        const uint32_t pa0 = f16x2(s[2 * kg][0],     s[2 * kg][1]);
        const uint32_t pa1 = f16x2(s[2 * kg][2],     s[2 * kg][3]);
        const uint32_t pa2 = f16x2(s[2 * kg + 1][0], s[2 * kg + 1][1]);
        const uint32_t pa3 = f16x2(s[2 * kg + 1][2], s[2 * kg + 1][3]);
#pragma unroll
        for (int nd = 0; nd < 8; nd++) {
          uint2 vfr = *(const uint2*)(vf + (nd * 4 + kg) * 256 + lane * 8);
          MMA_F16(o[nd], pa0, pa1, pa2, pa3, vfr);
        }
      }
    }

    CP_WAIT0();
    __syncthreads();
  }

  // ---- epilogue: normalize, write out[b, q, h*64 + d] ----
  const float i0 = 1.f / l0;
  const float i1 = 1.f / l1;
  const int rg = q0 + warp * 16 + (lane >> 2);
#pragma unroll
  for (int nd = 0; nd < 8; nd++) {
    const int gc = h * HSD + nd * 8 + lr2;
    float2 w0 = make_float2(o[nd][0] * i0, o[nd][1] * i0);
    float2 w1 = make_float2(o[nd][2] * i1, o[nd][3] * i1);
    *(float2*)&out[(size_t)(b * TSZ + rg) * CSZ + gc] = w0;
    *(float2*)&out[(size_t)(b * TSZ + rg + 8) * CSZ + gc] = w1;
  }
}

// ---------------------------------------------------------------------------
extern "C" void kernel_launch(void* const* d_in, const int* in_sizes, int n_in,
                              void* d_out, int out_size) {
  const float* x    = (const float*)d_in[0];
  const float* W    = (const float*)d_in[1];
  const float* bias = (const float*)d_in[2];
  float* out = (float*)d_out;

  (void)in_sizes; (void)n_in; (void)out_size;

  dim3 gp0(32, 56);
  gemm_frag_prep_kernel<<<gp0, 256>>>(x, W);

  cudaFuncSetAttribute(qkv_gemm_mma_kernel,
                       cudaFuncAttributeMaxDynamicSharedMemorySize,
                       GSMEM_TOTAL);
  dim3 g1(NC3 / 128, (BSZ * TSZ) / 128);   // (24, 32)
  qkv_gemm_mma_kernel<<<g1, 256, GSMEM_TOTAL>>>(bias);

  dim3 gp1(48, NH, BSZ);                   // 16 Q tiles + 32 KV tiles
  qkv_frag_prep_kernel<<<gp1, 256>>>();

  cudaFuncSetAttribute(flash_attn_mma_kernel,
                       cudaFuncAttributeMaxDynamicSharedMemorySize, FSMEM);
  dim3 g2(TSZ / FTQ, NH, BSZ);             // (16, 16, 2)
  flash_attn_mma_kernel<<<g2, 256, FSMEM>>>(out);
}

// round 16
// speedup vs baseline: 1.9657x; 1.0081x over previous
#include <cuda_runtime.h>
#include <math.h>
#include <stdint.h>

// Problem constants
#define BSZ   2
#define TSZ   2048
#define CSZ   1024
#define NH    16
#define HSD   64
#define NC3   3072   // 3*C

// Scratch: qkv = x @ W + b   [B, T, 3C]  (f32)
__device__ float g_qkv[(size_t)BSZ * TSZ * NC3];
// fp16 fragment images (packed half2 words)
__device__ uint32_t g_afrag[(size_t)32 * 32 * 2048];   // [m_blk][chunk][8KB]
__device__ uint32_t g_bfrag[(size_t)24 * 32 * 2048];   // [n_blk][chunk][8KB]
__device__ uint32_t g_qfrag[(size_t)BSZ * NH * 16 * 4096];   // [b][h][qt][16KB]
__device__ uint32_t g_kvfrag[(size_t)BSZ * NH * 32 * 4096];  // [b][h][kt][K8K+V8K]

// Q pre-scale: (1/sqrt(64)) * log2(e)  -> softmax in exp2 domain
#define QSCALE 0.18033688011112042f

// ===========================================================================
// helpers
// ===========================================================================
__device__ __forceinline__ float ex2f(float x) {
  float r;
  asm("ex2.approx.f32 %0, %1;" : "=f"(r) : "f"(x));
  return r;
}
__device__ __forceinline__ uint32_t h2ex2(uint32_t x) {
  uint32_t r;
  asm("ex2.approx.f16x2 %0, %1;" : "=r"(r) : "r"(x));
  return r;
}
__device__ __forceinline__ uint32_t smem_u32(const void* p) {
  uint32_t a;
  asm("{ .reg .u64 t; cvta.to.shared.u64 t, %1; cvt.u32.u64 %0, t; }"
      : "=r"(a) : "l"(p));
  return a;
}
// pack two f32 -> f16x2 (lo = first arg, hi = second)
__device__ __forceinline__ uint32_t f16x2(float lo, float hi) {
  uint32_t r;
  asm("cvt.rn.f16x2.f32 %0, %1, %2;" : "=r"(r) : "f"(hi), "f"(lo));
  return r;
}
#define MMA_F16(d, a0, a1, a2, a3, b0, b1)                                 \
  asm volatile(                                                            \
      "mma.sync.aligned.m16n8k16.row.col.f32.f16.f16.f32 "                 \
      "{%0,%1,%2,%3}, {%4,%5,%6,%7}, {%8,%9}, {%0,%1,%2,%3};"              \
      : "+f"((d)[0]), "+f"((d)[1]), "+f"((d)[2]), "+f"((d)[3])             \
      : "r"(a0), "r"(a1), "r"(a2), "r"(a3), "r"(b0), "r"(b1))
#define MMA_F16V(d, av, b0, b1)                                            \
  MMA_F16(d, (av).x, (av).y, (av).z, (av).w, b0, b1)
#define CP_ASYNC16(dst, src)                                               \
  asm volatile("cp.async.cg.shared.global [%0], [%1], 16;"                 \
               :: "r"(dst), "l"(src))
#define CP_COMMIT() asm volatile("cp.async.commit_group;" ::: "memory")
#define CP_WAIT0()  asm volatile("cp.async.wait_group 0;" ::: "memory")
#define CP_WAIT1()  asm volatile("cp.async.wait_group 1;" ::: "memory")

#define H2_ONE 0x3C003C00u   // half2(1.0, 1.0)

// ===========================================================================
// Kernel 0: build fp16 GEMM operand fragment images from x and W (R15).
// ===========================================================================
__global__ __launch_bounds__(256) void gemm_frag_prep_kernel(
    const float* __restrict__ A,
    const float* __restrict__ W) {
  const int tid = threadIdx.x;
  const int c = blockIdx.x;            // k-chunk 0..31 (32 floats each)
  const int k0 = c * 32;
  if (blockIdx.y < 32) {
    const int m0 = blockIdx.y * 128;
    char* img = (char*)g_afrag + ((size_t)(blockIdx.y * 32 + c)) * 8192;
#pragma unroll
    for (int i = 0; i < 2; i++) {
      const int u = tid + i * 256;       // 512 units
      const int g = u >> 5, lane = u & 31;
      const int tile = g >> 1, ks = g & 1;
      const int r = lane >> 2, t = lane & 3;
      const float* ap = A + (size_t)(m0 + tile * 16 + r) * CSZ + k0 + ks * 16;
      float2 p00 = *(const float2*)(ap + 2 * t);
      float2 p01 = *(const float2*)(ap + 2 * t + 8);
      float2 p10 = *(const float2*)(ap + 8 * CSZ + 2 * t);
      float2 p11 = *(const float2*)(ap + 8 * CSZ + 2 * t + 8);
      uint4 v;
      v.x = f16x2(p00.x, p00.y);
      v.y = f16x2(p10.x, p10.y);
      v.z = f16x2(p01.x, p01.y);
      v.w = f16x2(p11.x, p11.y);
      *(uint4*)(img + g * 512 + lane * 16) = v;
    }
  } else {
    const int n_blk = blockIdx.y - 32;
    const int n0 = n_blk * 128;
    char* img = (char*)g_bfrag + ((size_t)(n_blk * 32 + c)) * 8192;
#pragma unroll
    for (int i = 0; i < 4; i++) {
      const int u = tid + i * 256;       // 1024 units
      const int g = u >> 5, lane = u & 31;
      const int ntile = g >> 1, ks = g & 1;
      const int gq = lane >> 2, t = lane & 3;
      const int n = n0 + ntile * 8 + gq;
      const float* wp = W + (size_t)(k0 + ks * 16 + 2 * t) * NC3 + n;
      float w0 = wp[0];
      float w1 = wp[NC3];
      float w2 = wp[(size_t)8 * NC3];
      float w3 = wp[(size_t)9 * NC3];
      uint2 v;
      v.x = f16x2(w0, w1);
      v.y = f16x2(w2, w3);
      *(uint2*)(img + g * 256 + lane * 8) = v;
    }
  }
}

// ===========================================================================
// Kernel 1: QKV GEMM from fp16 fragments (R15, unchanged).
// ===========================================================================
#define GCHUNK 16384
#define GSMEM_TOTAL (3 * GCHUNK)
#define NCHUNK 32

__global__ __launch_bounds__(256, 2) void qkv_gemm_mma_kernel(
    const float* __restrict__ bias) {
  extern __shared__ char smem[];
  const uint32_t sb = smem_u32(smem);
  const int tid  = threadIdx.x;
  const int lane = tid & 31;
  const int warp = tid >> 5;
  const int wm = warp >> 2;
  const int wn = warp & 3;
  const int m0 = blockIdx.y * 128;
  const int n0 = blockIdx.x * 128;

  const char* asrc0 = (const char*)g_afrag + ((size_t)blockIdx.y * 32) * 8192;
  const char* bsrc0 = (const char*)g_bfrag + ((size_t)blockIdx.x * 32) * 8192;

  float acc[4][4][4] = {};

#pragma unroll
  for (int i = 0; i < 2; i++) {
    const int off = tid * 16 + i * 4096;
    CP_ASYNC16(sb + off, asrc0 + off);
    CP_ASYNC16(sb + 8192 + off, bsrc0 + off);
  }
  CP_COMMIT();

  for (int c = 0; c < NCHUNK; c++) {
    if (c + 1 < NCHUNK) {
      const uint32_t dst = sb + ((c + 1) % 3) * GCHUNK;
      const char* as = asrc0 + (size_t)(c + 1) * 8192;
      const char* bs = bsrc0 + (size_t)(c + 1) * 8192;
#pragma unroll
      for (int i = 0; i < 2; i++) {
        const int off = tid * 16 + i * 4096;
        CP_ASYNC16(dst + off, as + off);
        CP_ASYNC16(dst + 8192 + off, bs + off);
      }
      CP_COMMIT();
      CP_WAIT1();
    } else {
      CP_WAIT0();
    }
    __syncthreads();

    const char* ab = smem + (c % 3) * GCHUNK;
    const char* bb = ab + 8192;
#pragma unroll
    for (int ks = 0; ks < 2; ks++) {
      uint4 af[4];
      uint2 bf[4];
#pragma unroll
      for (int mi = 0; mi < 4; mi++)
        af[mi] = *(const uint4*)(ab + (((wm * 4 + mi) * 2 + ks) * 512) +
                                 lane * 16);
#pragma unroll
      for (int ni = 0; ni < 4; ni++)
        bf[ni] = *(const uint2*)(bb + (((wn * 4 + ni) * 2 + ks) * 256) +
                                 lane * 8);
#pragma unroll
      for (int mi = 0; mi < 4; mi++)
#pragma unroll
        for (int ni = 0; ni < 4; ni++)
          MMA_F16V(acc[mi][ni], af[mi], bf[ni].x, bf[ni].y);
    }
  }

  const int r_base = m0 + wm * 64 + (lane >> 2);
  const int c_base = n0 + wn * 32 + 2 * (lane & 3);
#pragma unroll
  for (int ni = 0; ni < 4; ni++) {
    const int gc = c_base + ni * 8;
    float2 bv = *(const float2*)&bias[gc];
#pragma unroll
    for (int mi = 0; mi < 4; mi++) {
      const int gr = r_base + mi * 16;
      float2 o0 = make_float2(acc[mi][ni][0] + bv.x, acc[mi][ni][1] + bv.y);
      float2 o1 = make_float2(acc[mi][ni][2] + bv.x, acc[mi][ni][3] + bv.y);
      *(float2*)&g_qkv[(size_t)gr * NC3 + gc] = o0;
      *(float2*)&g_qkv[(size_t)(gr + 8) * NC3 + gc] = o1;
    }
  }
}

// ===========================================================================
// Kernel 1.5: build fp16 Q / K / V fragment images from g_qkv.
// K and V use PAIR-INTERLEAVED layout: lane's 16B at
// (oct*2 + (ks>>1))*512 + lane*16 holds the uint2 operands for ks and ks^1
// -> flash reads one LDS.128 feeding two k16 MMAs.
// ===========================================================================
__global__ __launch_bounds__(256) void qkv_frag_prep_kernel() {
  const int tid = threadIdx.x;
  const int h = blockIdx.y;
  const int b = blockIdx.z;
  const float* qkv = g_qkv;

  if (blockIdx.x < 16) {
    const int qt = blockIdx.x;
    const int q0 = qt * 128;
    char* qimg = (char*)g_qfrag + ((size_t)((b * NH + h) * 16 + qt)) * 16384;
#pragma unroll
    for (int i = 0; i < 4; i++) {
      const int u = tid + i * 256;       // 1024 units
      const int g = u >> 5, lane = u & 31;
      const int wt = g >> 2, ks = g & 3;
      const int r = lane >> 2, t = lane & 3;
      const float* qp = qkv + (size_t)(b * TSZ + q0 + wt * 16 + r) * NC3 +
                        h * HSD + ks * 16;
      float2 p00 = *(const float2*)(qp + 2 * t);
      float2 p01 = *(const float2*)(qp + 2 * t + 8);
      float2 p10 = *(const float2*)(qp + (size_t)8 * NC3 + 2 * t);
      float2 p11 = *(const float2*)(qp + (size_t)8 * NC3 + 2 * t + 8);
      uint4 v;
      v.x = f16x2(p00.x * QSCALE, p00.y * QSCALE);
      v.y = f16x2(p10.x * QSCALE, p10.y * QSCALE);
      v.z = f16x2(p01.x * QSCALE, p01.y * QSCALE);
      v.w = f16x2(p11.x * QSCALE, p11.y * QSCALE);
      *(uint4*)(qimg + g * 512 + lane * 16) = v;
    }
  } else {
    const int kt = blockIdx.x - 16;
    const int k0 = kt * 64;
    char* kvimg = (char*)g_kvfrag + ((size_t)((b * NH + h) * 32 + kt)) * 16384;

    // K: pair-interleaved groups
#pragma unroll
    for (int i = 0; i < 4; i++) {
      const int u = tid + i * 256;       // 1024 units
      const int g = u >> 5, lane = u & 31;
      const int nt = g >> 2, ks = g & 3;
      const int t = lane & 3;
      const float* kp = qkv +
          (size_t)(b * TSZ + k0 + nt * 8 + (lane >> 2)) * NC3 + CSZ +
          h * HSD + ks * 16;
      float2 ka = *(const float2*)(kp + 2 * t);
      float2 kb = *(const float2*)(kp + 2 * t + 8);
      uint2 v;
      v.x = f16x2(ka.x, ka.y);
      v.y = f16x2(kb.x, kb.y);
      *(uint2*)(kvimg + (nt * 2 + (ks >> 1)) * 512 + lane * 16 +
                (ks & 1) * 8) = v;
    }

    // V: pair-interleaved groups
#pragma unroll
    for (int i = 0; i < 4; i++) {
      const int u = tid + i * 256;       // 1024 units
      const int g = u >> 5, lane = u & 31;
      const int nd = g >> 2, kg = g & 3;
      const int t = lane & 3;
      const int d = nd * 8 + (lane >> 2);
      const size_t base = (size_t)(b * TSZ + k0 + kg * 16) * NC3 +
                          2 * CSZ + h * HSD + d;
      float v0 = qkv[base + (size_t)(2 * t) * NC3];
      float v1 = qkv[base + (size_t)(2 * t + 1) * NC3];
      float v2 = qkv[base + (size_t)(2 * t + 8) * NC3];
      float v3 = qkv[base + (size_t)(2 * t + 9) * NC3];
      uint2 v;
      v.x = f16x2(v0, v1);
      v.y = f16x2(v2, v3);
      *(uint2*)(kvimg + 8192 + (nd * 2 + (kg >> 1)) * 512 + lane * 16 +
                (kg & 1) * 8) = v;
    }
  }
}

// ===========================================================================
// Kernel 2: flash attention, fp16 m16n8k16.
// - K/V paired LDS.128 reads (one load feeds two MMAs)
// - softmax: ex2.approx.f16x2 produces P fragments directly
// - row sums via 4 ones-MMAs (no shuffle reduction for l)
// Smem: Q 16KB + 2x16KB KV = 48KB.
// ===========================================================================
#define FTQ 128
#define FTK 64
#define FBUF0 16384
#define FSMEM (48 * 1024)

__global__ __launch_bounds__(256, 2) void flash_attn_mma_kernel(
    float* __restrict__ out) {
  extern __shared__ char fsm[];
  const uint32_t sb = smem_u32(fsm);
  const int tid  = threadIdx.x;
  const int lane = tid & 31;
  const int warp = tid >> 5;
  const int qt = gridDim.x - 1 - blockIdx.x;   // heavy tiles first
  const int h  = blockIdx.y;
  const int b  = blockIdx.z;
  const int q0 = qt * FTQ;
  const char* qimg =
      (const char*)g_qfrag + ((size_t)((b * NH + h) * 16 + qt)) * 16384;
  const char* tiles =
      (const char*)g_kvfrag + ((size_t)((b * NH + h) * 32)) * 16384;

  // prologue: Q image + KV tile 0
#pragma unroll
  for (int i = 0; i < 4; i++) {
    const int c = (tid + i * 256) * 16;
    CP_ASYNC16(sb + c, qimg + c);
    CP_ASYNC16(sb + FBUF0 + c, tiles + c);
  }
  CP_COMMIT();
  CP_WAIT0();
  __syncthreads();

  float m0 = -1e30f, m1 = -1e30f, l0 = 0.f, l1 = 0.f;
  float o[8][4] = {};
  const int wrow0 = q0 + warp * 16;
  const int r0g = wrow0 + (lane >> 2);
  const int r1g = r0g + 8;
  const int lr2 = 2 * (lane & 3);
  const int last_kt = 2 * qt + 1;

  for (int kt = 0; kt <= last_kt; kt++) {
    const int cur = kt & 1;

    if (kt < last_kt) {
      const char* src = tiles + (size_t)(kt + 1) * 16384;
      const uint32_t dst = sb + FBUF0 + (1 - cur) * 16384;
#pragma unroll
      for (int i = 0; i < 4; i++) {
        const int c = (tid + i * 256) * 16;
        CP_ASYNC16(dst + c, src + c);
      }
      CP_COMMIT();
    }

    const int k0 = kt * FTK;
    if (k0 <= wrow0 + 15) {
      const char* kf = fsm + FBUF0 + cur * 16384;
      const char* vf = kf + 8192;

      // ---- S = Q K^T  (2 ks-pairs x 8 token-octets; paired K reads) ----
      float s[8][4];
#pragma unroll
      for (int nt = 0; nt < 8; nt++)
        s[nt][0] = s[nt][1] = s[nt][2] = s[nt][3] = 0.f;
#pragma unroll
      for (int pp = 0; pp < 2; pp++) {
        uint4 qf0 = *(const uint4*)(fsm + (warp * 4 + 2 * pp) * 512 +
                                    lane * 16);
        uint4 qf1 = *(const uint4*)(fsm + (warp * 4 + 2 * pp + 1) * 512 +
                                    lane * 16);
#pragma unroll
        for (int nt = 0; nt < 8; nt++) {
          uint4 kk = *(const uint4*)(kf + (nt * 2 + pp) * 512 + lane * 16);
          MMA_F16V(s[nt], qf0, kk.x, kk.y);
          MMA_F16V(s[nt], qf1, kk.z, kk.w);
        }
      }

      // ---- causal mask ----
      if (k0 + FTK - 1 > wrow0) {
#pragma unroll
        for (int nt = 0; nt < 8; nt++) {
          const int cg = k0 + nt * 8 + lr2;
          if (cg     > r0g) s[nt][0] = -1e30f;
          if (cg + 1 > r0g) s[nt][1] = -1e30f;
          if (cg     > r1g) s[nt][2] = -1e30f;
          if (cg + 1 > r1g) s[nt][3] = -1e30f;
        }
      }

      // ---- running max (quad-reduced) ----
      float mx0 = -1e30f, mx1 = -1e30f;
#pragma unroll
      for (int nt = 0; nt < 8; nt++) {
        mx0 = fmaxf(mx0, fmaxf(s[nt][0], s[nt][1]));
        mx1 = fmaxf(mx1, fmaxf(s[nt][2], s[nt][3]));
      }
      mx0 = fmaxf(mx0, __shfl_xor_sync(0xffffffffu, mx0, 1));
      mx0 = fmaxf(mx0, __shfl_xor_sync(0xffffffffu, mx0, 2));
      mx1 = fmaxf(mx1, __shfl_xor_sync(0xffffffffu, mx1, 1));
      mx1 = fmaxf(mx1, __shfl_xor_sync(0xffffffffu, mx1, 2));
      const float mn0 = fmaxf(m0, mx0);
      const float mn1 = fmaxf(m1, mx1);
      const float al0 = ex2f(m0 - mn0);
      const float al1 = ex2f(m1 - mn1);

      // ---- P fragments via ex2.approx.f16x2 (direct fp16 A-frags) ----
      uint32_t pa[4][4];
#pragma unroll
      for (int kg = 0; kg < 4; kg++) {
        pa[kg][0] = h2ex2(f16x2(s[2 * kg][0] - mn0,     s[2 * kg][1] - mn0));
        pa[kg][1] = h2ex2(f16x2(s[2 * kg][2] - mn1,     s[2 * kg][3] - mn1));
        pa[kg][2] = h2ex2(f16x2(s[2 * kg + 1][0] - mn0, s[2 * kg + 1][1] - mn0));
        pa[kg][3] = h2ex2(f16x2(s[2 * kg + 1][2] - mn1, s[2 * kg + 1][3] - mn1));
      }

      // ---- tile row-sums via ones-MMA (cross-lane reduce for free) ----
      float ts[4] = {0.f, 0.f, 0.f, 0.f};
#pragma unroll
      for (int kg = 0; kg < 4; kg++)
        MMA_F16(ts, pa[kg][0], pa[kg][1], pa[kg][2], pa[kg][3],
                H2_ONE, H2_ONE);
      m0 = mn0; m1 = mn1;
      l0 = l0 * al0 + ts[0];
      l1 = l1 * al1 + ts[2];

      // ---- O = O*alpha + P V  (paired V reads) ----
#pragma unroll
      for (int nt = 0; nt < 8; nt++) {
        o[nt][0] *= al0; o[nt][1] *= al0;
        o[nt][2] *= al1; o[nt][3] *= al1;
      }
#pragma unroll
      for (int pp = 0; pp < 2; pp++) {
#pragma unroll
        for (int nd = 0; nd < 8; nd++) {
          uint4 vv = *(const uint4*)(vf + (nd * 2 + pp) * 512 + lane * 16);
          MMA_F16(o[nd], pa[2 * pp][0], pa[2 * pp][1], pa[2 * pp][2],
                  pa[2 * pp][3], vv.x, vv.y);
          MMA_F16(o[nd], pa[2 * pp + 1][0], pa[2 * pp + 1][1],
                  pa[2 * pp + 1][2], pa[2 * pp + 1][3], vv.z, vv.w);
        }
      }
    }

    CP_WAIT0();
    __syncthreads();
  }

  // ---- epilogue: normalize, write out[b, q, h*64 + d] ----
  const float i0 = 1.f / l0;
  const float i1 = 1.f / l1;
  const int rg = q0 + warp * 16 + (lane >> 2);
#pragma unroll
  for (int nd = 0; nd < 8; nd++) {
    const int gc = h * HSD + nd * 8 + lr2;
    float2 w0 = make_float2(o[nd][0] * i0, o[nd][1] * i0);
    float2 w1 = make_float2(o[nd][2] * i1, o[nd][3] * i1);
    *(float2*)&out[(size_t)(b * TSZ + rg) * CSZ + gc] = w0;
    *(float2*)&out[(size_t)(b * TSZ + rg + 8) * CSZ + gc] = w1;
  }
}

// ---------------------------------------------------------------------------
extern "C" void kernel_launch(void* const* d_in, const int* in_sizes, int n_in,
                              void* d_out, int out_size) {
  const float* x    = (const float*)d_in[0];
  const float* W    = (const float*)d_in[1];
  const float* bias = (const float*)d_in[2];
  float* out = (float*)d_out;

  (void)in_sizes; (void)n_in; (void)out_size;

  dim3 gp0(32, 56);
  gemm_frag_prep_kernel<<<gp0, 256>>>(x, W);

  cudaFuncSetAttribute(qkv_gemm_mma_kernel,
                       cudaFuncAttributeMaxDynamicSharedMemorySize,
                       GSMEM_TOTAL);
  dim3 g1(NC3 / 128, (BSZ * TSZ) / 128);   // (24, 32)
  qkv_gemm_mma_kernel<<<g1, 256, GSMEM_TOTAL>>>(bias);

  dim3 gp1(48, NH, BSZ);                   // 16 Q tiles + 32 KV tiles
  qkv_frag_prep_kernel<<<gp1, 256>>>();

  cudaFuncSetAttribute(flash_attn_mma_kernel,
                       cudaFuncAttributeMaxDynamicSharedMemorySize, FSMEM);
  dim3 g2(TSZ / FTQ, NH, BSZ);             // (16, 16, 2)
  flash_attn_mma_kernel<<<g2, 256, FSMEM>>>(out);
}

// round 17
// speedup vs baseline: 2.1003x; 1.0685x over previous
#include <cuda_runtime.h>
#include <cuda_fp16.h>
#include <math.h>
#include <stdint.h>

// Problem constants
#define BSZ   2
#define TSZ   2048
#define CSZ   1024
#define NH    16
#define HSD   64
#define NC3   3072   // 3*C

// Scratch: qkv in fp16 (Q third pre-scaled by QSCALE)   [B, T, 3C]
__device__ __half g_qkvh[(size_t)BSZ * TSZ * NC3];
// fp16 fragment images (packed half2 words)
__device__ uint32_t g_afrag[(size_t)32 * 32 * 2048];   // [m_blk][chunk][8KB]
__device__ uint32_t g_bfrag[(size_t)24 * 32 * 2048];   // [n_blk][chunk][8KB]
__device__ uint32_t g_qfrag[(size_t)BSZ * NH * 16 * 4096];   // [b][h][qt][16KB]
__device__ uint32_t g_kvfrag[(size_t)BSZ * NH * 32 * 4096];  // [b][h][kt][K8K+V8K]

// Q pre-scale: (1/sqrt(64)) * log2(e)  -> softmax in exp2 domain
#define QSCALE 0.18033688011112042f

// ===========================================================================
// helpers
// ===========================================================================
__device__ __forceinline__ float ex2f(float x) {
  float r;
  asm("ex2.approx.f32 %0, %1;" : "=f"(r) : "f"(x));
  return r;
}
__device__ __forceinline__ uint32_t h2ex2(uint32_t x) {
  uint32_t r;
  asm("ex2.approx.f16x2 %0, %1;" : "=r"(r) : "r"(x));
  return r;
}
__device__ __forceinline__ uint32_t smem_u32(const void* p) {
  uint32_t a;
  asm("{ .reg .u64 t; cvta.to.shared.u64 t, %1; cvt.u32.u64 %0, t; }"
      : "=r"(a) : "l"(p));
  return a;
}
// pack two f32 -> f16x2 (lo = first arg, hi = second)
__device__ __forceinline__ uint32_t f16x2(float lo, float hi) {
  uint32_t r;
  asm("cvt.rn.f16x2.f32 %0, %1, %2;" : "=r"(r) : "f"(hi), "f"(lo));
  return r;
}
#define MMA_F16(d, a0, a1, a2, a3, b0, b1)                                 \
  asm volatile(                                                            \
      "mma.sync.aligned.m16n8k16.row.col.f32.f16.f16.f32 "                 \
      "{%0,%1,%2,%3}, {%4,%5,%6,%7}, {%8,%9}, {%0,%1,%2,%3};"              \
      : "+f"((d)[0]), "+f"((d)[1]), "+f"((d)[2]), "+f"((d)[3])             \
      : "r"(a0), "r"(a1), "r"(a2), "r"(a3), "r"(b0), "r"(b1))
#define MMA_F16V(d, av, b0, b1)                                            \
  MMA_F16(d, (av).x, (av).y, (av).z, (av).w, b0, b1)
#define CP_ASYNC16(dst, src)                                               \
  asm volatile("cp.async.cg.shared.global [%0], [%1], 16;"                 \
               :: "r"(dst), "l"(src))
#define CP_COMMIT() asm volatile("cp.async.commit_group;" ::: "memory")
#define CP_WAIT0()  asm volatile("cp.async.wait_group 0;" ::: "memory")
#define CP_WAIT1()  asm volatile("cp.async.wait_group 1;" ::: "memory")

#define H2_ONE 0x3C003C00u   // half2(1.0, 1.0)

// ===========================================================================
// Kernel 0: build fp16 GEMM operand fragment images from x and W.
// ===========================================================================
__global__ __launch_bounds__(256) void gemm_frag_prep_kernel(
    const float* __restrict__ A,
    const float* __restrict__ W) {
  const int tid = threadIdx.x;
  const int c = blockIdx.x;            // k-chunk 0..31 (32 floats each)
  const int k0 = c * 32;
  if (blockIdx.y < 32) {
    const int m0 = blockIdx.y * 128;
    char* img = (char*)g_afrag + ((size_t)(blockIdx.y * 32 + c)) * 8192;
#pragma unroll
    for (int i = 0; i < 2; i++) {
      const int u = tid + i * 256;       // 512 units
      const int g = u >> 5, lane = u & 31;
      const int tile = g >> 1, ks = g & 1;
      const int r = lane >> 2, t = lane & 3;
      const float* ap = A + (size_t)(m0 + tile * 16 + r) * CSZ + k0 + ks * 16;
      float2 p00 = *(const float2*)(ap + 2 * t);
      float2 p01 = *(const float2*)(ap + 2 * t + 8);
      float2 p10 = *(const float2*)(ap + 8 * CSZ + 2 * t);
      float2 p11 = *(const float2*)(ap + 8 * CSZ + 2 * t + 8);
      uint4 v;
      v.x = f16x2(p00.x, p00.y);
      v.y = f16x2(p10.x, p10.y);
      v.z = f16x2(p01.x, p01.y);
      v.w = f16x2(p11.x, p11.y);
      *(uint4*)(img + g * 512 + lane * 16) = v;
    }
  } else {
    const int n_blk = blockIdx.y - 32;
    const int n0 = n_blk * 128;
    char* img = (char*)g_bfrag + ((size_t)(n_blk * 32 + c)) * 8192;
#pragma unroll
    for (int i = 0; i < 4; i++) {
      const int u = tid + i * 256;       // 1024 units
      const int g = u >> 5, lane = u & 31;
      const int ntile = g >> 1, ks = g & 1;
      const int gq = lane >> 2, t = lane & 3;
      const int n = n0 + ntile * 8 + gq;
      const float* wp = W + (size_t)(k0 + ks * 16 + 2 * t) * NC3 + n;
      float w0 = wp[0];
      float w1 = wp[NC3];
      float w2 = wp[(size_t)8 * NC3];
      float w3 = wp[(size_t)9 * NC3];
      uint2 v;
      v.x = f16x2(w0, w1);
      v.y = f16x2(w2, w3);
      *(uint2*)(img + g * 256 + lane * 8) = v;
    }
  }
}

// ===========================================================================
// Kernel 1: QKV GEMM from fp16 fragments.  Epilogue writes fp16 g_qkvh,
// with QSCALE pre-applied to the Q third (gc < CSZ).
// ===========================================================================
#define GCHUNK 16384
#define GSMEM_TOTAL (3 * GCHUNK)
#define NCHUNK 32

__global__ __launch_bounds__(256, 2) void qkv_gemm_mma_kernel(
    const float* __restrict__ bias) {
  extern __shared__ char smem[];
  const uint32_t sb = smem_u32(smem);
  const int tid  = threadIdx.x;
  const int lane = tid & 31;
  const int warp = tid >> 5;
  const int wm = warp >> 2;
  const int wn = warp & 3;
  const int m0 = blockIdx.y * 128;
  const int n0 = blockIdx.x * 128;

  const char* asrc0 = (const char*)g_afrag + ((size_t)blockIdx.y * 32) * 8192;
  const char* bsrc0 = (const char*)g_bfrag + ((size_t)blockIdx.x * 32) * 8192;

  float acc[4][4][4] = {};

#pragma unroll
  for (int i = 0; i < 2; i++) {
    const int off = tid * 16 + i * 4096;
    CP_ASYNC16(sb + off, asrc0 + off);
    CP_ASYNC16(sb + 8192 + off, bsrc0 + off);
  }
  CP_COMMIT();

  for (int c = 0; c < NCHUNK; c++) {
    if (c + 1 < NCHUNK) {
      const uint32_t dst = sb + ((c + 1) % 3) * GCHUNK;
      const char* as = asrc0 + (size_t)(c + 1) * 8192;
      const char* bs = bsrc0 + (size_t)(c + 1) * 8192;
#pragma unroll
      for (int i = 0; i < 2; i++) {
        const int off = tid * 16 + i * 4096;
        CP_ASYNC16(dst + off, as + off);
        CP_ASYNC16(dst + 8192 + off, bs + off);
      }
      CP_COMMIT();
      CP_WAIT1();
    } else {
      CP_WAIT0();
    }
    __syncthreads();

    const char* ab = smem + (c % 3) * GCHUNK;
    const char* bb = ab + 8192;
#pragma unroll
    for (int ks = 0; ks < 2; ks++) {
      uint4 af[4];
      uint2 bf[4];
#pragma unroll
      for (int mi = 0; mi < 4; mi++)
        af[mi] = *(const uint4*)(ab + (((wm * 4 + mi) * 2 + ks) * 512) +
                                 lane * 16);
#pragma unroll
      for (int ni = 0; ni < 4; ni++)
        bf[ni] = *(const uint2*)(bb + (((wn * 4 + ni) * 2 + ks) * 256) +
                                 lane * 8);
#pragma unroll
      for (int mi = 0; mi < 4; mi++)
#pragma unroll
        for (int ni = 0; ni < 4; ni++)
          MMA_F16V(acc[mi][ni], af[mi], bf[ni].x, bf[ni].y);
    }
  }

  // epilogue: acc + bias -> g_qkvh (fp16), QSCALE folded into Q columns
  const int r_base = m0 + wm * 64 + (lane >> 2);
  const int c_base = n0 + wn * 32 + 2 * (lane & 3);
#pragma unroll
  for (int ni = 0; ni < 4; ni++) {
    const int gc = c_base + ni * 8;
    float2 bv = *(const float2*)&bias[gc];
    const float sc = (gc < CSZ) ? QSCALE : 1.0f;
#pragma unroll
    for (int mi = 0; mi < 4; mi++) {
      const int gr = r_base + mi * 16;
      uint32_t p0 = f16x2((acc[mi][ni][0] + bv.x) * sc,
                          (acc[mi][ni][1] + bv.y) * sc);
      uint32_t p1 = f16x2((acc[mi][ni][2] + bv.x) * sc,
                          (acc[mi][ni][3] + bv.y) * sc);
      *(uint32_t*)&g_qkvh[(size_t)gr * NC3 + gc] = p0;
      *(uint32_t*)&g_qkvh[(size_t)(gr + 8) * NC3 + gc] = p1;
    }
  }
}

// ===========================================================================
// Kernel 1.5: relayout fp16 qkv into fragment images (pure copies, no cvt).
// Grid (48, 16, 2): x<16 -> Q tile qt=x; x>=16 -> KV tile kt=x-16.
// K/V pair-interleaved: group (oct*2 + ks/2)*512, halves at +(ks&1)*8.
// ===========================================================================
__global__ __launch_bounds__(256) void qkv_frag_prep_kernel() {
  const int tid = threadIdx.x;
  const int h = blockIdx.y;
  const int b = blockIdx.z;
  const __half* qkvh = g_qkvh;

  if (blockIdx.x < 16) {
    const int qt = blockIdx.x;
    const int q0 = qt * 128;
    char* qimg = (char*)g_qfrag + ((size_t)((b * NH + h) * 16 + qt)) * 16384;
#pragma unroll
    for (int i = 0; i < 4; i++) {
      const int u = tid + i * 256;       // 1024 units
      const int g = u >> 5, lane = u & 31;
      const int wt = g >> 2, ks = g & 3;
      const int r = lane >> 2, t = lane & 3;
      const __half* qp = qkvh + (size_t)(b * TSZ + q0 + wt * 16 + r) * NC3 +
                         h * HSD + ks * 16;
      uint4 v;
      v.x = *(const uint32_t*)(qp + 2 * t);
      v.y = *(const uint32_t*)(qp + (size_t)8 * NC3 + 2 * t);
      v.z = *(const uint32_t*)(qp + 2 * t + 8);
      v.w = *(const uint32_t*)(qp + (size_t)8 * NC3 + 2 * t + 8);
      *(uint4*)(qimg + g * 512 + lane * 16) = v;
    }
  } else {
    const int kt = blockIdx.x - 16;
    const int k0 = kt * 64;
    char* kvimg = (char*)g_kvfrag + ((size_t)((b * NH + h) * 32 + kt)) * 16384;

    // K: pair-interleaved groups (pure uint copies)
#pragma unroll
    for (int i = 0; i < 4; i++) {
      const int u = tid + i * 256;       // 1024 units
      const int g = u >> 5, lane = u & 31;
      const int nt = g >> 2, ks = g & 3;
      const int t = lane & 3;
      const __half* kp = qkvh +
          (size_t)(b * TSZ + k0 + nt * 8 + (lane >> 2)) * NC3 + CSZ +
          h * HSD + ks * 16;
      uint2 v;
      v.x = *(const uint32_t*)(kp + 2 * t);
      v.y = *(const uint32_t*)(kp + 2 * t + 8);
      *(uint2*)(kvimg + (nt * 2 + (ks >> 1)) * 512 + lane * 16 +
                (ks & 1) * 8) = v;
    }

    // V: pair-interleaved groups (ushort gathers)
#pragma unroll
    for (int i = 0; i < 4; i++) {
      const int u = tid + i * 256;       // 1024 units
      const int g = u >> 5, lane = u & 31;
      const int nd = g >> 2, kg = g & 3;
      const int t = lane & 3;
      const int d = nd * 8 + (lane >> 2);
      const __half* base = qkvh + (size_t)(b * TSZ + k0 + kg * 16) * NC3 +
                           2 * CSZ + h * HSD + d;
      uint32_t a0 = *(const uint16_t*)(base + (size_t)(2 * t) * NC3);
      uint32_t a1 = *(const uint16_t*)(base + (size_t)(2 * t + 1) * NC3);
      uint32_t a2 = *(const uint16_t*)(base + (size_t)(2 * t + 8) * NC3);
      uint32_t a3 = *(const uint16_t*)(base + (size_t)(2 * t + 9) * NC3);
      uint2 v;
      v.x = a0 | (a1 << 16);
      v.y = a2 | (a3 << 16);
      *(uint2*)(kvimg + 8192 + (nd * 2 + (kg >> 1)) * 512 + lane * 16 +
                (kg & 1) * 8) = v;
    }
  }
}

// ===========================================================================
// Kernel 2: flash attention, fp16 m16n8k16.
// - Q held in REGISTERS (one LDG burst per warp; no Q smem / cp.async)
// - K/V paired LDS.128 reads; ex2.approx.f16x2 P; ones-MMA row sums
// Smem: 2x16KB KV double buffer = 32KB.
// ===========================================================================
#define FTQ 128
#define FTK 64
#define FSMEM (32 * 1024)

__global__ __launch_bounds__(256, 2) void flash_attn_mma_kernel(
    float* __restrict__ out) {
  extern __shared__ char fsm[];
  const uint32_t sb = smem_u32(fsm);
  const int tid  = threadIdx.x;
  const int lane = tid & 31;
  const int warp = tid >> 5;
  const int qt = gridDim.x - 1 - blockIdx.x;   // heavy tiles first
  const int h  = blockIdx.y;
  const int b  = blockIdx.z;
  const int q0 = qt * FTQ;
  const char* qimg =
      (const char*)g_qfrag + ((size_t)((b * NH + h) * 16 + qt)) * 16384;
  const char* tiles =
      (const char*)g_kvfrag + ((size_t)((b * NH + h) * 32)) * 16384;

  // ---- Q fragments -> registers (16 regs/thread) ----
  uint4 qf[4];
#pragma unroll
  for (int ks = 0; ks < 4; ks++)
    qf[ks] = *(const uint4*)(qimg + (warp * 4 + ks) * 512 + lane * 16);

  // prologue: KV tile 0
#pragma unroll
  for (int i = 0; i < 4; i++) {
    const int c = (tid + i * 256) * 16;
    CP_ASYNC16(sb + c, tiles + c);
  }
  CP_COMMIT();
  CP_WAIT0();
  __syncthreads();

  float m0 = -1e30f, m1 = -1e30f, l0 = 0.f, l1 = 0.f;
  float o[8][4] = {};
  const int wrow0 = q0 + warp * 16;
  const int r0g = wrow0 + (lane >> 2);
  const int r1g = r0g + 8;
  const int lr2 = 2 * (lane & 3);
  const int last_kt = 2 * qt + 1;

  for (int kt = 0; kt <= last_kt; kt++) {
    const int cur = kt & 1;

    if (kt < last_kt) {
      const char* src = tiles + (size_t)(kt + 1) * 16384;
      const uint32_t dst = sb + (1 - cur) * 16384;
#pragma unroll
      for (int i = 0; i < 4; i++) {
        const int c = (tid + i * 256) * 16;
        CP_ASYNC16(dst + c, src + c);
      }
      CP_COMMIT();
    }

    const int k0 = kt * FTK;
    if (k0 <= wrow0 + 15) {
      const char* kf = fsm + cur * 16384;
      const char* vf = kf + 8192;

      // ---- S = Q K^T ----
      float s[8][4];
#pragma unroll
      for (int nt = 0; nt < 8; nt++)
        s[nt][0] = s[nt][1] = s[nt][2] = s[nt][3] = 0.f;
#pragma unroll
      for (int pp = 0; pp < 2; pp++) {
#pragma unroll
        for (int nt = 0; nt < 8; nt++) {
          uint4 kk = *(const uint4*)(kf + (nt * 2 + pp) * 512 + lane * 16);
          MMA_F16V(s[nt], qf[2 * pp], kk.x, kk.y);
          MMA_F16V(s[nt], qf[2 * pp + 1], kk.z, kk.w);
        }
      }

      // ---- causal mask ----
      if (k0 + FTK - 1 > wrow0) {
#pragma unroll
        for (int nt = 0; nt < 8; nt++) {
          const int cg = k0 + nt * 8 + lr2;
          if (cg     > r0g) s[nt][0] = -1e30f;
          if (cg + 1 > r0g) s[nt][1] = -1e30f;
          if (cg     > r1g) s[nt][2] = -1e30f;
          if (cg + 1 > r1g) s[nt][3] = -1e30f;
        }
      }

      // ---- running max (quad-reduced) ----
      float mx0 = -1e30f, mx1 = -1e30f;
#pragma unroll
      for (int nt = 0; nt < 8; nt++) {
        mx0 = fmaxf(mx0, fmaxf(s[nt][0], s[nt][1]));
        mx1 = fmaxf(mx1, fmaxf(s[nt][2], s[nt][3]));
      }
      mx0 = fmaxf(mx0, __shfl_xor_sync(0xffffffffu, mx0, 1));
      mx0 = fmaxf(mx0, __shfl_xor_sync(0xffffffffu, mx0, 2));
      mx1 = fmaxf(mx1, __shfl_xor_sync(0xffffffffu, mx1, 1));
      mx1 = fmaxf(mx1, __shfl_xor_sync(0xffffffffu, mx1, 2));
      const float mn0 = fmaxf(m0, mx0);
      const float mn1 = fmaxf(m1, mx1);
      const float al0 = ex2f(m0 - mn0);
      const float al1 = ex2f(m1 - mn1);

      // ---- P fragments via ex2.approx.f16x2 ----
      uint32_t pa[4][4];
#pragma unroll
      for (int kg = 0; kg < 4; kg++) {
        pa[kg][0] = h2ex2(f16x2(s[2 * kg][0] - mn0,     s[2 * kg][1] - mn0));
        pa[kg][1] = h2ex2(f16x2(s[2 * kg][2] - mn1,     s[2 * kg][3] - mn1));
        pa[kg][2] = h2ex2(f16x2(s[2 * kg + 1][0] - mn0, s[2 * kg + 1][1] - mn0));
        pa[kg][3] = h2ex2(f16x2(s[2 * kg + 1][2] - mn1, s[2 * kg + 1][3] - mn1));
      }

      // ---- tile row-sums via ones-MMA ----
      float ts[4] = {0.f, 0.f, 0.f, 0.f};
#pragma unroll
      for (int kg = 0; kg < 4; kg++)
        MMA_F16(ts, pa[kg][0], pa[kg][1], pa[kg][2], pa[kg][3],
                H2_ONE, H2_ONE);
      m0 = mn0; m1 = mn1;
      l0 = l0 * al0 + ts[0];
      l1 = l1 * al1 + ts[2];

      // ---- O = O*alpha + P V ----
#pragma unroll
      for (int nt = 0; nt < 8; nt++) {
        o[nt][0] *= al0; o[nt][1] *= al0;
        o[nt][2] *= al1; o[nt][3] *= al1;
      }
#pragma unroll
      for (int pp = 0; pp < 2; pp++) {
#pragma unroll
        for (int nd = 0; nd < 8; nd++) {
          uint4 vv = *(const uint4*)(vf + (nd * 2 + pp) * 512 + lane * 16);
          MMA_F16(o[nd], pa[2 * pp][0], pa[2 * pp][1], pa[2 * pp][2],
                  pa[2 * pp][3], vv.x, vv.y);
          MMA_F16(o[nd], pa[2 * pp + 1][0], pa[2 * pp + 1][1],
                  pa[2 * pp + 1][2], pa[2 * pp + 1][3], vv.z, vv.w);
        }
      }
    }

    CP_WAIT0();
    __syncthreads();
  }

  // ---- epilogue: normalize, write out[b, q, h*64 + d] ----
  const float i0 = 1.f / l0;
  const float i1 = 1.f / l1;
  const int rg = q0 + warp * 16 + (lane >> 2);
#pragma unroll
  for (int nd = 0; nd < 8; nd++) {
    const int gc = h * HSD + nd * 8 + lr2;
    float2 w0 = make_float2(o[nd][0] * i0, o[nd][1] * i0);
    float2 w1 = make_float2(o[nd][2] * i1, o[nd][3] * i1);
    *(float2*)&out[(size_t)(b * TSZ + rg) * CSZ + gc] = w0;
    *(float2*)&out[(size_t)(b * TSZ + rg + 8) * CSZ + gc] = w1;
  }
}

// ---------------------------------------------------------------------------
extern "C" void kernel_launch(void* const* d_in, const int* in_sizes, int n_in,
                              void* d_out, int out_size) {
  const float* x    = (const float*)d_in[0];
  const float* W    = (const float*)d_in[1];
  const float* bias = (const float*)d_in[2];
  float* out = (float*)d_out;

  (void)in_sizes; (void)n_in; (void)out_size;

  dim3 gp0(32, 56);
  gemm_frag_prep_kernel<<<gp0, 256>>>(x, W);

  cudaFuncSetAttribute(qkv_gemm_mma_kernel,
                       cudaFuncAttributeMaxDynamicSharedMemorySize,
                       GSMEM_TOTAL);
  dim3 g1(NC3 / 128, (BSZ * TSZ) / 128);   // (24, 32)
  qkv_gemm_mma_kernel<<<g1, 256, GSMEM_TOTAL>>>(bias);

  dim3 gp1(48, NH, BSZ);                   // 16 Q tiles + 32 KV tiles
  qkv_frag_prep_kernel<<<gp1, 256>>>();

  cudaFuncSetAttribute(flash_attn_mma_kernel,
                       cudaFuncAttributeMaxDynamicSharedMemorySize, FSMEM);
  dim3 g2(TSZ / FTQ, NH, BSZ);             // (16, 16, 2)
  flash_attn_mma_kernel<<<g2, 256, FSMEM>>>(out);
}